// round 12
// baseline (speedup 1.0000x reference)
#include <cuda_runtime.h>
#include <cuda_fp16.h>
#include <math.h>

#define T_   2
#define NP   25000
#define EP   200000
#define HID_ 256
#define NTOT (T_*NP)
#define E2   (2*EP)

// ---------------- scratch (static __device__ — no allocations) ----------------
__device__ __half g_hnh[(size_t)T_*NP*HID_];      // fp16 LN out (conv paths)
__device__ float  g_q  [(size_t)NTOT*HID_];       // fp32 q (read once per node)
__device__ __half g_kvh[(size_t)NTOT*512];        // fp16 k|v per node
__device__ float  g_sc [(size_t)E2*8];            // ex values (CSR order)
__device__ float  g_cs [T_*NP];
__device__ float  g_cd [T_*NP];
__device__ float  g_qkvb[T_*768];
__device__ int    g_degs[T_*NP];
__device__ int    g_degd[T_*NP];
__device__ int    g_bsum[256];
// CSR by global dst node
__device__ int    g_off [NTOT + 1];
__device__ int    g_fill[NTOT];
__device__ int    g_csr [E2];
// fp16 A operands
__device__ __half g_ah[(size_t)NTOT*HID_];
__device__ __half g_fh[(size_t)NTOT*512];
// split weights, fp16 hi/lo, layout [matrix][t][N][K]
#define WCVT_TOTAL 1310720
__device__ __half g_whi[WCVT_TOTAL];
__device__ __half g_wlo[WCVT_TOTAL];
#define WOFF_PRE  0
#define WOFF_POST 131072
#define WOFF_QKV  262144
#define WOFF_O    655360
#define WOFF_F1   786432
#define WOFF_F2   1048576

// ---------------- mma / async helpers ----------------
__device__ __forceinline__ unsigned smem_u32(const void* p) {
    unsigned a;
    asm("{ .reg .u64 t; cvta.to.shared.u64 t, %1; cvt.u32.u64 %0, t; }" : "=r"(a) : "l"(p));
    return a;
}
#define LDM4(r, a) \
    asm volatile("ldmatrix.sync.aligned.m8n8.x4.shared.b16 {%0,%1,%2,%3}, [%4];" \
        : "=r"((r)[0]),"=r"((r)[1]),"=r"((r)[2]),"=r"((r)[3]) : "r"(a))
#define MMA_F16(c, a, b0, b1) \
    asm volatile("mma.sync.aligned.m16n8k16.row.col.f32.f16.f16.f32 " \
        "{%0,%1,%2,%3}, {%4,%5,%6,%7}, {%8,%9}, {%0,%1,%2,%3};" \
        : "+f"((c)[0]),"+f"((c)[1]),"+f"((c)[2]),"+f"((c)[3]) \
        : "r"((a)[0]),"r"((a)[1]),"r"((a)[2]),"r"((a)[3]), "r"(b0),"r"(b1))
#define CP16(dst, src) \
    asm volatile("cp.async.cg.shared.global [%0], [%1], 16;" :: "r"(dst), "l"(src) : "memory")
#define CP_COMMIT() asm volatile("cp.async.commit_group;" ::: "memory")
#define CP_WAIT0()  asm volatile("cp.async.wait_group 0;" ::: "memory")

__device__ __forceinline__ void store_h4(__half* dst, float4 v) {
    __half2 p0 = __floats2half2_rn(v.x, v.y);
    __half2 p1 = __floats2half2_rn(v.z, v.w);
    uint2 u;
    u.x = *(unsigned*)&p0; u.y = *(unsigned*)&p1;
    *(uint2*)dst = u;
}
__device__ __forceinline__ float4 load_h4(const __half* src) {
    uint2 u = *(const uint2*)src;
    __half2 p0 = *(__half2*)&u.x;
    __half2 p1 = *(__half2*)&u.y;
    float2 f0 = __half22float2(p0);
    float2 f1 = __half22float2(p1);
    return make_float4(f0.x, f0.y, f1.x, f1.y);
}
__device__ __forceinline__ float warp_sum(float v) {
    #pragma unroll
    for (int o = 16; o; o >>= 1) v += __shfl_xor_sync(0xffffffffu, v, o);
    return v;
}

// ---------------- degree + CSR build ----------------
__global__ void k_deg(const int* __restrict__ es, const int* __restrict__ ed) {
    int gid = blockIdx.x * blockDim.x + threadIdx.x;
    if (gid >= E2) return;
    int et = gid / EP;
    atomicAdd(&g_degs[et*NP + es[gid]], 1);
    atomicAdd(&g_degd[et*NP + ed[gid]], 1);
}

__global__ void k_degnorm() {
    int n = blockIdx.x * blockDim.x + threadIdx.x;
    if (n >= NP) return;
    #pragma unroll
    for (int et = 0; et < 2; et++) {
        g_cs[et*NP + n]       = rsqrtf((float)max(g_degs[et*NP + n], 1));
        g_cd[(1-et)*NP + n]   = rsqrtf((float)max(g_degd[et*NP + n], 1));
    }
}

// ---------------- parallel exclusive scan of in-degrees -> g_off ----------------
__global__ void k_scan1() {
    __shared__ int wsum[8];
    int tid = threadIdx.x, lane = tid & 31, wid = tid >> 5;
    int g = blockIdx.x * 256 + tid;
    int deg = 0;
    if (g < NTOT) {
        int dt = g / NP, n = g - dt * NP;
        deg = g_degd[(1 - dt) * NP + n];
    }
    int x = deg;
    #pragma unroll
    for (int o = 1; o < 32; o <<= 1) { int y = __shfl_up_sync(~0u, x, o); if (lane >= o) x += y; }
    if (lane == 31) wsum[wid] = x;
    __syncthreads();
    if (tid == 0) { int s = 0; for (int i = 0; i < 8; i++) { int t2 = wsum[i]; wsum[i] = s; s += t2; } }
    __syncthreads();
    if (g < NTOT) g_off[g] = wsum[wid] + x - deg;
    if (tid == 255) g_bsum[blockIdx.x] = wsum[7] + x;
}

__global__ void k_scan2() {
    __shared__ int wsum[8];
    int tid = threadIdx.x, lane = tid & 31, wid = tid >> 5;
    int v = (tid < 196) ? g_bsum[tid] : 0;
    int x = v;
    #pragma unroll
    for (int o = 1; o < 32; o <<= 1) { int y = __shfl_up_sync(~0u, x, o); if (lane >= o) x += y; }
    if (lane == 31) wsum[wid] = x;
    __syncthreads();
    if (tid == 0) { int s = 0; for (int i = 0; i < 8; i++) { int t2 = wsum[i]; wsum[i] = s; s += t2; } }
    __syncthreads();
    int excl = wsum[wid] + x - v;
    if (tid < 196) g_bsum[tid] = excl;
    if (tid == 195) g_off[NTOT] = excl + v;
}

__global__ void k_scan3() {
    int g = blockIdx.x * 256 + threadIdx.x;
    if (g < NTOT) g_off[g] += g_bsum[blockIdx.x];
}

__global__ void k_fill(const int* __restrict__ ed) {
    int gid = blockIdx.x * blockDim.x + threadIdx.x;
    if (gid >= E2) return;
    int et = gid / EP;
    int gnode = (1 - et) * NP + ed[gid];
    int pos = g_off[gnode] + atomicAdd(&g_fill[gnode], 1);
    g_csr[pos] = gid;
}

// ---------------- layernorm: warp per node, fp16 out (all paths) ----------------
__global__ void k_lnh(const float* __restrict__ x, const float* __restrict__ g,
                      const float* __restrict__ b, __half* __restrict__ dst) {
    int gn = blockIdx.x * 8 + (threadIdx.x >> 5);
    int lane = threadIdx.x & 31;
    int t = gn / NP;
    size_t base = (size_t)gn * HID_ + lane * 8;
    float4 v0 = *(const float4*)&x[base];
    float4 v1 = *(const float4*)&x[base + 4];
    float s = v0.x+v0.y+v0.z+v0.w + v1.x+v1.y+v1.z+v1.w;
    float mu = warp_sum(s) * (1.0f / HID_);
    float d0x=v0.x-mu, d0y=v0.y-mu, d0z=v0.z-mu, d0w=v0.w-mu;
    float d1x=v1.x-mu, d1y=v1.y-mu, d1z=v1.z-mu, d1w=v1.w-mu;
    float ss = d0x*d0x+d0y*d0y+d0z*d0z+d0w*d0w + d1x*d1x+d1y*d1y+d1z*d1z+d1w*d1w;
    float rstd = rsqrtf(warp_sum(ss) * (1.0f / HID_) + 1e-5f);
    size_t pb = (size_t)t * HID_ + lane * 8;
    float4 g0 = *(const float4*)&g[pb],  g1 = *(const float4*)&g[pb + 4];
    float4 b0 = *(const float4*)&b[pb],  b1 = *(const float4*)&b[pb + 4];
    float4 o0, o1;
    o0.x = d0x*rstd*g0.x + b0.x; o0.y = d0y*rstd*g0.y + b0.y;
    o0.z = d0z*rstd*g0.z + b0.z; o0.w = d0w*rstd*g0.w + b0.w;
    o1.x = d1x*rstd*g1.x + b1.x; o1.y = d1y*rstd*g1.y + b1.y;
    o1.z = d1z*rstd*g1.z + b1.z; o1.w = d1w*rstd*g1.w + b1.w;
    store_h4(&dst[base],     o0);
    store_h4(&dst[base + 4], o1);
}

// ---------------- conv aggregation: CSR gather (fp16 rows), fp16 out ----------------
__global__ void __launch_bounds__(64) k_conv_gather(const int* __restrict__ es) {
    int gnode = blockIdx.x;
    int tid = threadIdx.x;
    int off = g_off[gnode], end = g_off[gnode + 1];
    int dt = gnode / NP;
    int et = 1 - dt;
    float4 acc = make_float4(0.f, 0.f, 0.f, 0.f);
    for (int i = off; i < end; i++) {
        int eid = g_csr[i];
        int src = es[eid];
        float w = g_cs[et*NP + src];
        float4 hv = load_h4(&g_hnh[((size_t)et*NP + src)*HID_ + tid*4]);
        acc.x += hv.x*w; acc.y += hv.y*w; acc.z += hv.z*w; acc.w += hv.w*w;
    }
    store_h4(&g_ah[(size_t)gnode*HID_ + tid*4], acc);
}

// ---------------- fused attention: score+exp+den+gather, fp16 out ----------------
// q: fp32 [node][256]; kv: fp16 [node][ k(0:256) | v(256:512) ]
#define ECACHE 160
__global__ void __launch_bounds__(64) k_attn(const float* __restrict__ q,
                                             const __half* __restrict__ kvh,
                                             const int* __restrict__ es) {
    __shared__ float sq[HID_];
    __shared__ float sden[2][8];
    __shared__ int ssrc[ECACHE];
    int gnode = blockIdx.x, tid = threadIdx.x, lane = tid & 31, wid = tid >> 5;
    int off = g_off[gnode], deg = g_off[gnode + 1] - off;

    *(float4*)&sq[tid*4] = *(const float4*)&q[(size_t)gnode*HID_ + tid*4];
    int ncache = (deg < ECACHE) ? deg : ECACHE;
    for (int i = tid; i < ncache; i += 64) {
        int eid = g_csr[off + i];
        int et = eid / EP;
        ssrc[i] = es[eid] + (et ? NP : 0);
    }
    __syncthreads();

    float denAcc = 0.f;
    for (int i = wid; i < deg; i += 2) {
        int sg;
        if (i < ECACHE) sg = ssrc[i];
        else { int eid = g_csr[off + i]; int et = eid / EP; sg = es[eid] + (et ? NP : 0); }
        const __half* kv = &kvh[(size_t)sg * 512];
        float myex = 0.f;
        #pragma unroll
        for (int hh = 0; hh < 8; hh++) {
            float p = sq[hh*32 + lane] * __half2float(kv[hh*32 + lane]);
            p = warp_sum(p);
            float s = fminf(fmaxf(p * 0.17677669529663687f, -5.0f), 5.0f);
            float ex = expf(s);   // s in [-5,5]: no overflow; max-shift cancels exactly
            if (lane == hh) myex = ex;
        }
        if (lane < 8) {
            g_sc[(size_t)(off + i)*8 + lane] = myex;
            denAcc += myex;
        }
    }
    if (lane < 8) sden[wid][lane] = denAcc;
    __syncthreads();

    int hh = tid >> 3;
    float den = sden[0][hh] + sden[1][hh];
    float rden = (den > 0.f) ? 1.0f / den : 0.f;
    float4 acc = make_float4(0.f, 0.f, 0.f, 0.f);
    for (int i = 0; i < deg; i++) {
        int sg;
        if (i < ECACHE) sg = ssrc[i];
        else { int eid = g_csr[off + i]; int et = eid / EP; sg = es[eid] + (et ? NP : 0); }
        float alpha = g_sc[(size_t)(off + i)*8 + hh] * rden;
        float4 vv = load_h4(&kvh[(size_t)sg*512 + 256 + tid*4]);
        acc.x += vv.x*alpha; acc.y += vv.y*alpha; acc.z += vv.z*alpha; acc.w += vv.w*alpha;
    }
    store_h4(&g_ah[(size_t)gnode*HID_ + tid*4], acc);
}

// ---------------- all-weights split to fp16 hi/lo (one launch) ----------------
__global__ void k_wconv_all(const float* __restrict__ preW, const float* __restrict__ postW,
                            const float* __restrict__ qW, const float* __restrict__ kW,
                            const float* __restrict__ vW, const float* __restrict__ oW,
                            const float* __restrict__ f1W, const float* __restrict__ f2W) {
    int gid = blockIdx.x * 256 + threadIdx.x;
    if (gid >= WCVT_TOTAL) return;
    float x;
    if (gid < 262144) {                       // PRE, POST: [t][256][256]
        const float* W = (gid < 131072) ? preW : postW;
        int loc = gid & 131071;
        int t = loc >> 16, o = loc & 65535;
        int n = o >> 8, kk = o & 255;
        x = W[t*65536 + kk*256 + n];
    } else if (gid < 655360) {                // QKV: [t][768][256]
        int loc = gid - 262144;
        int t = loc / 196608, r = loc % 196608;
        int n7 = r >> 8, kk = r & 255;
        const float* W; int n;
        if (n7 < 256)      { W = qW; n = n7; }
        else if (n7 < 512) { W = kW; n = n7 - 256; }
        else               { W = vW; n = n7 - 512; }
        x = W[t*65536 + kk*256 + n];
    } else if (gid < 786432) {                // O: [t][256][256]
        int loc = gid - 655360;
        int t = loc >> 16, o = loc & 65535;
        int n = o >> 8, kk = o & 255;
        x = oW[t*65536 + kk*256 + n];
    } else if (gid < 1048576) {               // F1: [t][512][256]
        int loc = gid - 786432;
        int t = loc >> 17, o = loc & 131071;
        int n = o >> 8, kk = o & 255;
        x = f1W[t*131072 + kk*512 + n];
    } else {                                  // F2: [t][256][512]
        int loc = gid - 1048576;
        int t = loc >> 17, o = loc & 131071;
        int n = o >> 9, kk = o & 511;
        x = f2W[t*131072 + kk*256 + n];
    }
    __half h = __float2half_rn(x);
    g_whi[gid] = h;
    g_wlo[gid] = __float2half_rn(x - __half2float(h));
}

__global__ void k_qkvb(const float* __restrict__ qB, const float* __restrict__ kB,
                       const float* __restrict__ vB) {
    int i = blockIdx.x * 256 + threadIdx.x;
    if (i >= T_ * 768) return;
    int t = i / 768, c = i % 768;
    g_qkvb[i] = (c < 256) ? qB[t*256 + c] : (c < 512) ? kB[t*256 + c - 256] : vB[t*256 + c - 512];
}

// ---------------- fp16 tensor GEMM: D = A*(Bhi+Blo), 2-stage cp.async ----------------
// outmode: 0 = fp32 C; 1 = fp16 Ch; 2 = qkv split (col<256 -> fp32 C stride 256,
//          col>=256 -> fp16 Ch stride 512)
#define PAD 40
#define ST_A   (128*PAD)
#define ST_ALL (3*128*PAD)
#define GSMEM  (2*ST_ALL*2)

__global__ void __launch_bounds__(256, 2) gemm_mma(
    const __half* __restrict__ A_g,
    const __half* __restrict__ Bhi_g, const __half* __restrict__ Blo_g,
    const float* __restrict__ bias, const float* __restrict__ rowscale,
    const float* __restrict__ resid, float* __restrict__ C,
    __half* __restrict__ Ch,
    int M, int K, int N, int wswap, int dogelu, int outmode)
{
    extern __shared__ __half smem[];

    int tid = threadIdx.x;
    int warp = tid >> 5, lane = tid & 31;
    int wm = warp & 3, wn = warp >> 2;
    int t = blockIdx.z;
    int wi = wswap ? (1 - t) : t;

    A_g   += (size_t)t  * M * K;
    Bhi_g += (size_t)wi * K * N;
    Blo_g += (size_t)wi * K * N;
    bias  += (size_t)wi * N;
    const float* rs = rowscale ? rowscale + (size_t)t * M : nullptr;
    const float* rd = resid ? resid + (size_t)t * M * N : nullptr;
    if (outmode == 2) {
        C  += (size_t)t * M * 256;
        Ch += (size_t)t * M * 512;
    } else {
        C += (size_t)t * M * N;
        if (Ch) Ch += (size_t)t * M * N;
    }

    int m0 = blockIdx.y * 128, n0 = blockIdx.x * 128;

    float acc[2][8][4];
    #pragma unroll
    for (int i = 0; i < 2; i++)
        #pragma unroll
        for (int j = 0; j < 8; j++)
            #pragma unroll
            for (int l = 0; l < 4; l++) acc[i][j][l] = 0.f;

    int lrow = lane & 7, lsel = lane >> 3;
    int a_r = (lsel & 1) * 8 + lrow;
    int a_c = (lsel >> 1) * 8;
    int b_r = (lsel >> 1) * 8 + lrow;
    int b_c = (lsel & 1) * 8;

    unsigned usm = smem_u32(smem);
    int grow = tid >> 2, gseg = tid & 3;
    int nchunks = K >> 5;

    {
        unsigned base = usm;
        #pragma unroll
        for (int i = 0; i < 2; i++) {
            int row = grow + i * 64;
            unsigned loc = 2u * (unsigned)(row * PAD + gseg * 8);
            size_t goa = (size_t)(m0 + row) * K + (gseg << 3);
            size_t gob = (size_t)(n0 + row) * K + (gseg << 3);
            CP16(base + loc,               &A_g[goa]);
            CP16(base + 2u*ST_A + loc,     &Bhi_g[gob]);
            CP16(base + 2u*2*ST_A + loc,   &Blo_g[gob]);
        }
        CP_COMMIT();
    }

    for (int c = 0; c < nchunks; c++) {
        int s = c & 1;
        unsigned base = usm + 2u * (unsigned)(s * ST_ALL);
        unsigned ua = base, ubh = base + 2u*ST_A, ubl = base + 2u*2*ST_A;

        CP_WAIT0();
        __syncthreads();

        if (c + 1 < nchunks) {
            int koff = (c + 1) << 5;
            unsigned nb = usm + 2u * (unsigned)((1 - s) * ST_ALL);
            #pragma unroll
            for (int i = 0; i < 2; i++) {
                int row = grow + i * 64;
                unsigned loc = 2u * (unsigned)(row * PAD + gseg * 8);
                size_t goa = (size_t)(m0 + row) * K + koff + (gseg << 3);
                size_t gob = (size_t)(n0 + row) * K + koff + (gseg << 3);
                CP16(nb + loc,             &A_g[goa]);
                CP16(nb + 2u*ST_A + loc,   &Bhi_g[gob]);
                CP16(nb + 2u*2*ST_A + loc, &Blo_g[gob]);
            }
            CP_COMMIT();
        }

        #pragma unroll
        for (int ks = 0; ks < 2; ks++) {
            int kk = ks * 16;
            unsigned ah[2][4];
            #pragma unroll
            for (int mt = 0; mt < 2; mt++) {
                unsigned off = 2u * (unsigned)((wm*32 + mt*16 + a_r) * PAD + kk + a_c);
                LDM4(ah[mt], ua + off);
            }
            #pragma unroll
            for (int bi = 0; bi < 4; bi++) {
                unsigned off = 2u * (unsigned)((wn*64 + bi*16 + b_r) * PAD + kk + b_c);
                unsigned bh[4], bl[4];
                LDM4(bh, ubh + off);
                LDM4(bl, ubl + off);
                #pragma unroll
                for (int mt = 0; mt < 2; mt++) {
                    #pragma unroll
                    for (int j = 0; j < 2; j++) {
                        float* cc = acc[mt][bi*2 + j];
                        MMA_F16(cc, ah[mt], bh[j*2], bh[j*2+1]);
                        MMA_F16(cc, ah[mt], bl[j*2], bl[j*2+1]);
                    }
                }
            }
        }
        __syncthreads();
    }

    int g = lane >> 2, tig = lane & 3;
    #pragma unroll
    for (int mt = 0; mt < 2; mt++) {
        #pragma unroll
        for (int nt = 0; nt < 8; nt++) {
            int col = n0 + wn*64 + nt*8 + tig*2;
            float b0 = bias[col], b1 = bias[col+1];
            #pragma unroll
            for (int half = 0; half < 2; half++) {
                int r = m0 + wm*32 + mt*16 + g + half*8;
                if (r >= M) continue;
                float scale = rs ? rs[r] : 1.0f;
                float2 o;
                o.x = acc[mt][nt][half*2+0] * scale + b0;
                o.y = acc[mt][nt][half*2+1] * scale + b1;
                if (rd) {
                    const float2 rv = *(const float2*)&rd[(size_t)r * N + col];
                    o.x += rv.x; o.y += rv.y;
                }
                if (dogelu) {
                    o.x = 0.5f*o.x*(1.0f+erff(o.x*0.70710678118654752f));
                    o.y = 0.5f*o.y*(1.0f+erff(o.y*0.70710678118654752f));
                }
                if (outmode == 2) {
                    if (col < 256) {
                        *(float2*)&C[(size_t)r * 256 + col] = o;
                    } else {
                        __half2 p = __floats2half2_rn(o.x, o.y);
                        *(unsigned*)&Ch[(size_t)r * 512 + col - 256] = *(unsigned*)&p;
                    }
                } else if (outmode == 1) {
                    __half2 p = __floats2half2_rn(o.x, o.y);
                    *(unsigned*)&Ch[(size_t)r * N + col] = *(unsigned*)&p;
                } else {
                    *(float2*)&C[(size_t)r * N + col] = o;
                }
            }
        }
    }
}

// ---------------- host orchestration ----------------
extern "C" void kernel_launch(void* const* d_in, const int* in_sizes, int n_in,
                              void* d_out, int out_size) {
    const float* h      = (const float*)d_in[0];
    const int*   es     = (const int*)  d_in[1];
    const int*   ed     = (const int*)  d_in[2];
    const float* preW   = (const float*)d_in[3];
    const float* preB   = (const float*)d_in[4];
    const float* postW  = (const float*)d_in[5];
    const float* postB  = (const float*)d_in[6];
    const float* qW     = (const float*)d_in[7];
    const float* qB     = (const float*)d_in[8];
    const float* kW     = (const float*)d_in[9];
    const float* kB     = (const float*)d_in[10];
    const float* vW     = (const float*)d_in[11];
    const float* vB     = (const float*)d_in[12];
    const float* oW     = (const float*)d_in[13];
    const float* oB     = (const float*)d_in[14];
    const float* fW1    = (const float*)d_in[15];
    const float* fB1    = (const float*)d_in[16];
    const float* fW2    = (const float*)d_in[17];
    const float* fB2    = (const float*)d_in[18];
    const float* lnPreG = (const float*)d_in[19];
    const float* lnPreB = (const float*)d_in[20];
    const float* lnAtG  = (const float*)d_in[21];
    const float* lnAtB  = (const float*)d_in[22];
    const float* lnPoG  = (const float*)d_in[23];
    const float* lnPoB  = (const float*)d_in[24];
    const float* lnFfG  = (const float*)d_in[25];
    const float* lnFfB  = (const float*)d_in[26];
    float* out = (float*)d_out;

    float *q, *cd, *qkvb;
    __half *whi, *wlo, *ah, *fh, *hnh, *kvh;
    int *degs, *degd, *fill;
    cudaGetSymbolAddress((void**)&hnh,  g_hnh);
    cudaGetSymbolAddress((void**)&q,    g_q);
    cudaGetSymbolAddress((void**)&kvh,  g_kvh);
    cudaGetSymbolAddress((void**)&cd,   g_cd);
    cudaGetSymbolAddress((void**)&qkvb, g_qkvb);
    cudaGetSymbolAddress((void**)&degs, g_degs);
    cudaGetSymbolAddress((void**)&degd, g_degd);
    cudaGetSymbolAddress((void**)&fill, g_fill);
    cudaGetSymbolAddress((void**)&whi,  g_whi);
    cudaGetSymbolAddress((void**)&wlo,  g_wlo);
    cudaGetSymbolAddress((void**)&ah,   g_ah);
    cudaGetSymbolAddress((void**)&fh,   g_fh);

    cudaFuncSetAttribute(gemm_mma, cudaFuncAttributeMaxDynamicSharedMemorySize, GSMEM);

    const dim3 g256(2, 196, 2);
    const dim3 g768(6, 196, 2);
    const dim3 g512(4, 196, 2);
    const int NB = (NTOT + 255) / 256;   // 196
    const int LNB = NTOT / 8;            // 6250

    // weights + bias + degrees + CSR
    k_wconv_all<<<WCVT_TOTAL/256, 256>>>(preW, postW, qW, kW, vW, oW, fW1, fW2);
    k_qkvb<<<(T_*768 + 255)/256, 256>>>(qB, kB, vB);
    cudaMemsetAsync(degs, 0, sizeof(int) * T_ * NP);
    cudaMemsetAsync(degd, 0, sizeof(int) * T_ * NP);
    cudaMemsetAsync(fill, 0, sizeof(int) * NTOT);
    k_deg<<<(E2 + 255)/256, 256>>>(es, ed);
    k_degnorm<<<(NP + 255)/256, 256>>>();
    k_scan1<<<NB, 256>>>();
    k_scan2<<<1, 256>>>();
    k_scan3<<<NB, 256>>>();
    k_fill<<<(E2 + 255)/256, 256>>>(ed);

    // ---- conv1 ----
    k_lnh<<<LNB, 256>>>(h, lnPreG, lnPreB, hnh);
    k_conv_gather<<<NTOT, 64>>>(es);
    gemm_mma<<<g256, 256, GSMEM>>>(ah, whi+WOFF_PRE, wlo+WOFF_PRE, preB, cd, h, out,
                                   nullptr, NP, HID_, HID_, 1, 0, 0);

    // ---- attention ----
    k_lnh<<<LNB, 256>>>(out, lnAtG, lnAtB, ah);
    gemm_mma<<<g768, 256, GSMEM>>>(ah, whi+WOFF_QKV, wlo+WOFF_QKV, qkvb, nullptr, nullptr,
                                   q, kvh, NP, HID_, 768, 0, 0, 2);
    k_attn<<<NTOT, 64>>>(q, kvh, es);
    gemm_mma<<<g256, 256, GSMEM>>>(ah, whi+WOFF_O, wlo+WOFF_O, oB, nullptr, out, out,
                                   nullptr, NP, HID_, HID_, 0, 0, 0);

    // ---- conv2 ----
    k_lnh<<<LNB, 256>>>(out, lnPoG, lnPoB, hnh);
    k_conv_gather<<<NTOT, 64>>>(es);
    gemm_mma<<<g256, 256, GSMEM>>>(ah, whi+WOFF_POST, wlo+WOFF_POST, postB, cd, out, out,
                                   nullptr, NP, HID_, HID_, 1, 0, 0);

    // ---- FFN ----
    k_lnh<<<LNB, 256>>>(out, lnFfG, lnFfB, ah);
    gemm_mma<<<g512, 256, GSMEM>>>(ah, whi+WOFF_F1, wlo+WOFF_F1, fB1, nullptr, nullptr,
                                   nullptr, fh, NP, HID_, 512, 0, 1, 1);
    gemm_mma<<<g256, 256, GSMEM>>>(fh, whi+WOFF_F2, wlo+WOFF_F2, fB2, nullptr, out, out,
                                   nullptr, NP, 512, HID_, 0, 0, 0);
}

// round 13
// speedup vs baseline: 1.0583x; 1.0583x over previous
#include <cuda_runtime.h>
#include <cuda_fp16.h>
#include <math.h>

#define T_   2
#define NP   25000
#define EP   200000
#define HID_ 256
#define NTOT (T_*NP)
#define E2   (2*EP)

// ---------------- scratch (static __device__ — no allocations) ----------------
__device__ __half g_hnh[(size_t)T_*NP*HID_];      // fp16 LN out (conv paths)
__device__ float  g_qkv[(size_t)NTOT*768];        // fp32 q|k|v per node
__device__ float  g_sc [(size_t)E2*8];            // ex values (CSR order)
__device__ float  g_cs [T_*NP];
__device__ float  g_cd [T_*NP];
__device__ float  g_qkvb[T_*768];
__device__ int    g_degs[T_*NP];
__device__ int    g_degd[T_*NP];
__device__ int    g_bsum[256];
// CSR by global dst node
__device__ int    g_off [NTOT + 1];
__device__ int    g_fill[NTOT];
__device__ int    g_csr [E2];
// fp16 A operands
__device__ __half g_ah[(size_t)NTOT*HID_];
__device__ __half g_fh[(size_t)NTOT*512];
// split weights, fp16 hi/lo, layout [matrix][t][N][K]
#define WCVT_TOTAL 1310720
__device__ __half g_whi[WCVT_TOTAL];
__device__ __half g_wlo[WCVT_TOTAL];
#define WOFF_PRE  0
#define WOFF_POST 131072
#define WOFF_QKV  262144
#define WOFF_O    655360
#define WOFF_F1   786432
#define WOFF_F2   1048576

// ---------------- mma / async helpers ----------------
__device__ __forceinline__ unsigned smem_u32(const void* p) {
    unsigned a;
    asm("{ .reg .u64 t; cvta.to.shared.u64 t, %1; cvt.u32.u64 %0, t; }" : "=r"(a) : "l"(p));
    return a;
}
#define LDM4(r, a) \
    asm volatile("ldmatrix.sync.aligned.m8n8.x4.shared.b16 {%0,%1,%2,%3}, [%4];" \
        : "=r"((r)[0]),"=r"((r)[1]),"=r"((r)[2]),"=r"((r)[3]) : "r"(a))
#define MMA_F16(c, a, b0, b1) \
    asm volatile("mma.sync.aligned.m16n8k16.row.col.f32.f16.f16.f32 " \
        "{%0,%1,%2,%3}, {%4,%5,%6,%7}, {%8,%9}, {%0,%1,%2,%3};" \
        : "+f"((c)[0]),"+f"((c)[1]),"+f"((c)[2]),"+f"((c)[3]) \
        : "r"((a)[0]),"r"((a)[1]),"r"((a)[2]),"r"((a)[3]), "r"(b0),"r"(b1))
#define CP16(dst, src) \
    asm volatile("cp.async.cg.shared.global [%0], [%1], 16;" :: "r"(dst), "l"(src) : "memory")
#define CP_COMMIT() asm volatile("cp.async.commit_group;" ::: "memory")
#define CP_WAIT0()  asm volatile("cp.async.wait_group 0;" ::: "memory")

__device__ __forceinline__ void store_h4(__half* dst, float4 v) {
    __half2 p0 = __floats2half2_rn(v.x, v.y);
    __half2 p1 = __floats2half2_rn(v.z, v.w);
    uint2 u;
    u.x = *(unsigned*)&p0; u.y = *(unsigned*)&p1;
    *(uint2*)dst = u;
}
__device__ __forceinline__ float4 load_h4(const __half* src) {
    uint2 u = *(const uint2*)src;
    __half2 p0 = *(__half2*)&u.x;
    __half2 p1 = *(__half2*)&u.y;
    float2 f0 = __half22float2(p0);
    float2 f1 = __half22float2(p1);
    return make_float4(f0.x, f0.y, f1.x, f1.y);
}
__device__ __forceinline__ float warp_sum(float v) {
    #pragma unroll
    for (int o = 16; o; o >>= 1) v += __shfl_xor_sync(0xffffffffu, v, o);
    return v;
}

// ---------------- degree + CSR build ----------------
__global__ void k_deg(const int* __restrict__ es, const int* __restrict__ ed) {
    int gid = blockIdx.x * blockDim.x + threadIdx.x;
    if (gid >= E2) return;
    int et = gid / EP;
    atomicAdd(&g_degs[et*NP + es[gid]], 1);
    atomicAdd(&g_degd[et*NP + ed[gid]], 1);
}

__global__ void k_degnorm() {
    int n = blockIdx.x * blockDim.x + threadIdx.x;
    if (n >= NP) return;
    #pragma unroll
    for (int et = 0; et < 2; et++) {
        g_cs[et*NP + n]       = rsqrtf((float)max(g_degs[et*NP + n], 1));
        g_cd[(1-et)*NP + n]   = rsqrtf((float)max(g_degd[et*NP + n], 1));
    }
}

// ---------------- parallel exclusive scan of in-degrees -> g_off ----------------
__global__ void k_scan1() {
    __shared__ int wsum[8];
    int tid = threadIdx.x, lane = tid & 31, wid = tid >> 5;
    int g = blockIdx.x * 256 + tid;
    int deg = 0;
    if (g < NTOT) {
        int dt = g / NP, n = g - dt * NP;
        deg = g_degd[(1 - dt) * NP + n];
    }
    int x = deg;
    #pragma unroll
    for (int o = 1; o < 32; o <<= 1) { int y = __shfl_up_sync(~0u, x, o); if (lane >= o) x += y; }
    if (lane == 31) wsum[wid] = x;
    __syncthreads();
    if (tid == 0) { int s = 0; for (int i = 0; i < 8; i++) { int t2 = wsum[i]; wsum[i] = s; s += t2; } }
    __syncthreads();
    if (g < NTOT) g_off[g] = wsum[wid] + x - deg;
    if (tid == 255) g_bsum[blockIdx.x] = wsum[7] + x;
}

__global__ void k_scan2() {
    __shared__ int wsum[8];
    int tid = threadIdx.x, lane = tid & 31, wid = tid >> 5;
    int v = (tid < 196) ? g_bsum[tid] : 0;
    int x = v;
    #pragma unroll
    for (int o = 1; o < 32; o <<= 1) { int y = __shfl_up_sync(~0u, x, o); if (lane >= o) x += y; }
    if (lane == 31) wsum[wid] = x;
    __syncthreads();
    if (tid == 0) { int s = 0; for (int i = 0; i < 8; i++) { int t2 = wsum[i]; wsum[i] = s; s += t2; } }
    __syncthreads();
    int excl = wsum[wid] + x - v;
    if (tid < 196) g_bsum[tid] = excl;
    if (tid == 195) g_off[NTOT] = excl + v;
}

__global__ void k_scan3() {
    int g = blockIdx.x * 256 + threadIdx.x;
    if (g < NTOT) g_off[g] += g_bsum[blockIdx.x];
}

__global__ void k_fill(const int* __restrict__ ed) {
    int gid = blockIdx.x * blockDim.x + threadIdx.x;
    if (gid >= E2) return;
    int et = gid / EP;
    int gnode = (1 - et) * NP + ed[gid];
    int pos = g_off[gnode] + atomicAdd(&g_fill[gnode], 1);
    g_csr[pos] = gid;
}

// ---------------- layernorm: warp per node, fp16 out to dst ----------------
__global__ void k_lnh(const float* __restrict__ x, const float* __restrict__ g,
                      const float* __restrict__ b, __half* __restrict__ dst) {
    int gn = blockIdx.x * 8 + (threadIdx.x >> 5);
    int lane = threadIdx.x & 31;
    int t = gn / NP;
    size_t base = (size_t)gn * HID_ + lane * 8;
    float4 v0 = *(const float4*)&x[base];
    float4 v1 = *(const float4*)&x[base + 4];
    float s = v0.x+v0.y+v0.z+v0.w + v1.x+v1.y+v1.z+v1.w;
    float mu = warp_sum(s) * (1.0f / HID_);
    float d0x=v0.x-mu, d0y=v0.y-mu, d0z=v0.z-mu, d0w=v0.w-mu;
    float d1x=v1.x-mu, d1y=v1.y-mu, d1z=v1.z-mu, d1w=v1.w-mu;
    float ss = d0x*d0x+d0y*d0y+d0z*d0z+d0w*d0w + d1x*d1x+d1y*d1y+d1z*d1z+d1w*d1w;
    float rstd = rsqrtf(warp_sum(ss) * (1.0f / HID_) + 1e-5f);
    size_t pb = (size_t)t * HID_ + lane * 8;
    float4 g0 = *(const float4*)&g[pb],  g1 = *(const float4*)&g[pb + 4];
    float4 b0 = *(const float4*)&b[pb],  b1 = *(const float4*)&b[pb + 4];
    float4 o0, o1;
    o0.x = d0x*rstd*g0.x + b0.x; o0.y = d0y*rstd*g0.y + b0.y;
    o0.z = d0z*rstd*g0.z + b0.z; o0.w = d0w*rstd*g0.w + b0.w;
    o1.x = d1x*rstd*g1.x + b1.x; o1.y = d1y*rstd*g1.y + b1.y;
    o1.z = d1z*rstd*g1.z + b1.z; o1.w = d1w*rstd*g1.w + b1.w;
    store_h4(&dst[base],     o0);
    store_h4(&dst[base + 4], o1);
}

// ---------------- conv aggregation: CSR gather (fp16 rows), fp16 out ----------------
__global__ void __launch_bounds__(64) k_conv_gather(const int* __restrict__ es) {
    int gnode = blockIdx.x;
    int tid = threadIdx.x;
    int off = g_off[gnode], end = g_off[gnode + 1];
    int dt = gnode / NP;
    int et = 1 - dt;
    float4 acc = make_float4(0.f, 0.f, 0.f, 0.f);
    for (int i = off; i < end; i++) {
        int eid = g_csr[i];
        int src = es[eid];
        float w = g_cs[et*NP + src];
        float4 hv = load_h4(&g_hnh[((size_t)et*NP + src)*HID_ + tid*4]);
        acc.x += hv.x*w; acc.y += hv.y*w; acc.z += hv.z*w; acc.w += hv.w*w;
    }
    store_h4(&g_ah[(size_t)gnode*HID_ + tid*4], acc);
}

// ---------------- fused attention: score+exp+den+gather, fp16 out ----------------
// qkv layout: [node][ q(0:256) | k(256:512) | v(512:768) ] fp32
#define ECACHE 160
__global__ void __launch_bounds__(64) k_attn(const float* __restrict__ qkv,
                                             const int* __restrict__ es) {
    __shared__ float sq[HID_];
    __shared__ float sden[2][8];
    __shared__ int ssrc[ECACHE];
    int gnode = blockIdx.x, tid = threadIdx.x, lane = tid & 31, wid = tid >> 5;
    int off = g_off[gnode], deg = g_off[gnode + 1] - off;

    *(float4*)&sq[tid*4] = *(const float4*)&qkv[(size_t)gnode*768 + tid*4];
    int ncache = (deg < ECACHE) ? deg : ECACHE;
    for (int i = tid; i < ncache; i += 64) {
        int eid = g_csr[off + i];
        int et = eid / EP;
        ssrc[i] = es[eid] + (et ? NP : 0);
    }
    __syncthreads();

    float denAcc = 0.f;
    for (int i = wid; i < deg; i += 2) {
        int sg;
        if (i < ECACHE) sg = ssrc[i];
        else { int eid = g_csr[off + i]; int et = eid / EP; sg = es[eid] + (et ? NP : 0); }
        const float* kv = &qkv[(size_t)sg * 768 + 256];
        float myex = 0.f;
        #pragma unroll
        for (int hh = 0; hh < 8; hh++) {
            float p = sq[hh*32 + lane] * kv[hh*32 + lane];
            p = warp_sum(p);
            float s = fminf(fmaxf(p * 0.17677669529663687f, -5.0f), 5.0f);
            float ex = expf(s);   // s in [-5,5]: no overflow; max-shift cancels exactly
            if (lane == hh) myex = ex;
        }
        if (lane < 8) {
            g_sc[(size_t)(off + i)*8 + lane] = myex;
            denAcc += myex;
        }
    }
    if (lane < 8) sden[wid][lane] = denAcc;
    __syncthreads();

    int hh = tid >> 3;
    float den = sden[0][hh] + sden[1][hh];
    float rden = (den > 0.f) ? 1.0f / den : 0.f;
    float4 acc = make_float4(0.f, 0.f, 0.f, 0.f);
    for (int i = 0; i < deg; i++) {
        int sg;
        if (i < ECACHE) sg = ssrc[i];
        else { int eid = g_csr[off + i]; int et = eid / EP; sg = es[eid] + (et ? NP : 0); }
        float alpha = g_sc[(size_t)(off + i)*8 + hh] * rden;
        const float4 vv = *(const float4*)&qkv[(size_t)sg*768 + 512 + tid*4];
        acc.x += vv.x*alpha; acc.y += vv.y*alpha; acc.z += vv.z*alpha; acc.w += vv.w*alpha;
    }
    store_h4(&g_ah[(size_t)gnode*HID_ + tid*4], acc);
}

// ---------------- all-weights split to fp16 hi/lo (one launch) ----------------
__global__ void k_wconv_all(const float* __restrict__ preW, const float* __restrict__ postW,
                            const float* __restrict__ qW, const float* __restrict__ kW,
                            const float* __restrict__ vW, const float* __restrict__ oW,
                            const float* __restrict__ f1W, const float* __restrict__ f2W) {
    int gid = blockIdx.x * 256 + threadIdx.x;
    if (gid >= WCVT_TOTAL) return;
    float x;
    if (gid < 262144) {                       // PRE, POST: [t][256][256]
        const float* W = (gid < 131072) ? preW : postW;
        int loc = gid & 131071;
        int t = loc >> 16, o = loc & 65535;
        int n = o >> 8, kk = o & 255;
        x = W[t*65536 + kk*256 + n];
    } else if (gid < 655360) {                // QKV: [t][768][256]
        int loc = gid - 262144;
        int t = loc / 196608, r = loc % 196608;
        int n7 = r >> 8, kk = r & 255;
        const float* W; int n;
        if (n7 < 256)      { W = qW; n = n7; }
        else if (n7 < 512) { W = kW; n = n7 - 256; }
        else               { W = vW; n = n7 - 512; }
        x = W[t*65536 + kk*256 + n];
    } else if (gid < 786432) {                // O: [t][256][256]
        int loc = gid - 655360;
        int t = loc >> 16, o = loc & 65535;
        int n = o >> 8, kk = o & 255;
        x = oW[t*65536 + kk*256 + n];
    } else if (gid < 1048576) {               // F1: [t][512][256]
        int loc = gid - 786432;
        int t = loc >> 17, o = loc & 131071;
        int n = o >> 8, kk = o & 255;
        x = f1W[t*131072 + kk*512 + n];
    } else {                                  // F2: [t][256][512]
        int loc = gid - 1048576;
        int t = loc >> 17, o = loc & 131071;
        int n = o >> 9, kk = o & 511;
        x = f2W[t*131072 + kk*256 + n];
    }
    __half h = __float2half_rn(x);
    g_whi[gid] = h;
    g_wlo[gid] = __float2half_rn(x - __half2float(h));
}

__global__ void k_qkvb(const float* __restrict__ qB, const float* __restrict__ kB,
                       const float* __restrict__ vB) {
    int i = blockIdx.x * 256 + threadIdx.x;
    if (i >= T_ * 768) return;
    int t = i / 768, c = i % 768;
    g_qkvb[i] = (c < 256) ? qB[t*256 + c] : (c < 512) ? kB[t*256 + c - 256] : vB[t*256 + c - 512];
}

// ---------------- fp16 tensor GEMM: D = A*(Bhi+Blo), 2-stage cp.async ----------------
// A fp16 [t][M][K]; B split fp16 hi/lo [t][N][K].
// CTA 128x128, 8 warps (4m x 2n), K-chunk 32.
#define PAD 40
#define ST_A   (128*PAD)
#define ST_ALL (3*128*PAD)
#define GSMEM  (2*ST_ALL*2)

__global__ void __launch_bounds__(256, 2) gemm_mma(
    const __half* __restrict__ A_g,
    const __half* __restrict__ Bhi_g, const __half* __restrict__ Blo_g,
    const float* __restrict__ bias, const float* __restrict__ rowscale,
    const float* __restrict__ resid, float* __restrict__ C,
    __half* __restrict__ Ch,
    int M, int K, int N, int wswap, int dogelu)
{
    extern __shared__ __half smem[];

    int tid = threadIdx.x;
    int warp = tid >> 5, lane = tid & 31;
    int wm = warp & 3, wn = warp >> 2;
    int t = blockIdx.z;
    int wi = wswap ? (1 - t) : t;

    A_g   += (size_t)t  * M * K;
    Bhi_g += (size_t)wi * K * N;
    Blo_g += (size_t)wi * K * N;
    bias  += (size_t)wi * N;
    const float* rs = rowscale ? rowscale + (size_t)t * M : nullptr;
    const float* rd = resid ? resid + (size_t)t * M * N : nullptr;
    C  += (size_t)t * M * N;
    if (Ch) Ch += (size_t)t * M * N;

    int m0 = blockIdx.y * 128, n0 = blockIdx.x * 128;

    float acc[2][8][4];
    #pragma unroll
    for (int i = 0; i < 2; i++)
        #pragma unroll
        for (int j = 0; j < 8; j++)
            #pragma unroll
            for (int l = 0; l < 4; l++) acc[i][j][l] = 0.f;

    int lrow = lane & 7, lsel = lane >> 3;
    int a_r = (lsel & 1) * 8 + lrow;
    int a_c = (lsel >> 1) * 8;
    int b_r = (lsel >> 1) * 8 + lrow;
    int b_c = (lsel & 1) * 8;

    unsigned usm = smem_u32(smem);
    int grow = tid >> 2, gseg = tid & 3;
    int nchunks = K >> 5;

    {
        unsigned base = usm;
        #pragma unroll
        for (int i = 0; i < 2; i++) {
            int row = grow + i * 64;
            unsigned loc = 2u * (unsigned)(row * PAD + gseg * 8);
            size_t goa = (size_t)(m0 + row) * K + (gseg << 3);
            size_t gob = (size_t)(n0 + row) * K + (gseg << 3);
            CP16(base + loc,               &A_g[goa]);
            CP16(base + 2u*ST_A + loc,     &Bhi_g[gob]);
            CP16(base + 2u*2*ST_A + loc,   &Blo_g[gob]);
        }
        CP_COMMIT();
    }

    for (int c = 0; c < nchunks; c++) {
        int s = c & 1;
        unsigned base = usm + 2u * (unsigned)(s * ST_ALL);
        unsigned ua = base, ubh = base + 2u*ST_A, ubl = base + 2u*2*ST_A;

        CP_WAIT0();
        __syncthreads();

        if (c + 1 < nchunks) {
            int koff = (c + 1) << 5;
            unsigned nb = usm + 2u * (unsigned)((1 - s) * ST_ALL);
            #pragma unroll
            for (int i = 0; i < 2; i++) {
                int row = grow + i * 64;
                unsigned loc = 2u * (unsigned)(row * PAD + gseg * 8);
                size_t goa = (size_t)(m0 + row) * K + koff + (gseg << 3);
                size_t gob = (size_t)(n0 + row) * K + koff + (gseg << 3);
                CP16(nb + loc,             &A_g[goa]);
                CP16(nb + 2u*ST_A + loc,   &Bhi_g[gob]);
                CP16(nb + 2u*2*ST_A + loc, &Blo_g[gob]);
            }
            CP_COMMIT();
        }

        #pragma unroll
        for (int ks = 0; ks < 2; ks++) {
            int kk = ks * 16;
            unsigned ah[2][4];
            #pragma unroll
            for (int mt = 0; mt < 2; mt++) {
                unsigned off = 2u * (unsigned)((wm*32 + mt*16 + a_r) * PAD + kk + a_c);
                LDM4(ah[mt], ua + off);
            }
            #pragma unroll
            for (int bi = 0; bi < 4; bi++) {
                unsigned off = 2u * (unsigned)((wn*64 + bi*16 + b_r) * PAD + kk + b_c);
                unsigned bh[4], bl[4];
                LDM4(bh, ubh + off);
                LDM4(bl, ubl + off);
                #pragma unroll
                for (int mt = 0; mt < 2; mt++) {
                    #pragma unroll
                    for (int j = 0; j < 2; j++) {
                        float* cc = acc[mt][bi*2 + j];
                        MMA_F16(cc, ah[mt], bh[j*2], bh[j*2+1]);
                        MMA_F16(cc, ah[mt], bl[j*2], bl[j*2+1]);
                    }
                }
            }
        }
        __syncthreads();
    }

    int g = lane >> 2, tig = lane & 3;
    #pragma unroll
    for (int mt = 0; mt < 2; mt++) {
        #pragma unroll
        for (int nt = 0; nt < 8; nt++) {
            int col = n0 + wn*64 + nt*8 + tig*2;
            float b0 = bias[col], b1 = bias[col+1];
            #pragma unroll
            for (int half = 0; half < 2; half++) {
                int r = m0 + wm*32 + mt*16 + g + half*8;
                if (r >= M) continue;
                float scale = rs ? rs[r] : 1.0f;
                size_t idx = (size_t)r * N + col;
                float2 o;
                o.x = acc[mt][nt][half*2+0] * scale + b0;
                o.y = acc[mt][nt][half*2+1] * scale + b1;
                if (rd) {
                    const float2 rv = *(const float2*)&rd[idx];
                    o.x += rv.x; o.y += rv.y;
                }
                if (dogelu) {
                    o.x = 0.5f*o.x*(1.0f+erff(o.x*0.70710678118654752f));
                    o.y = 0.5f*o.y*(1.0f+erff(o.y*0.70710678118654752f));
                }
                if (Ch) {
                    __half2 p = __floats2half2_rn(o.x, o.y);
                    *(unsigned*)&Ch[idx] = *(unsigned*)&p;
                } else {
                    *(float2*)&C[idx] = o;
                }
            }
        }
    }
}

// ---------------- host orchestration ----------------
extern "C" void kernel_launch(void* const* d_in, const int* in_sizes, int n_in,
                              void* d_out, int out_size) {
    const float* h      = (const float*)d_in[0];
    const int*   es     = (const int*)  d_in[1];
    const int*   ed     = (const int*)  d_in[2];
    const float* preW   = (const float*)d_in[3];
    const float* preB   = (const float*)d_in[4];
    const float* postW  = (const float*)d_in[5];
    const float* postB  = (const float*)d_in[6];
    const float* qW     = (const float*)d_in[7];
    const float* qB     = (const float*)d_in[8];
    const float* kW     = (const float*)d_in[9];
    const float* kB     = (const float*)d_in[10];
    const float* vW     = (const float*)d_in[11];
    const float* vB     = (const float*)d_in[12];
    const float* oW     = (const float*)d_in[13];
    const float* oB     = (const float*)d_in[14];
    const float* fW1    = (const float*)d_in[15];
    const float* fB1    = (const float*)d_in[16];
    const float* fW2    = (const float*)d_in[17];
    const float* fB2    = (const float*)d_in[18];
    const float* lnPreG = (const float*)d_in[19];
    const float* lnPreB = (const float*)d_in[20];
    const float* lnAtG  = (const float*)d_in[21];
    const float* lnAtB  = (const float*)d_in[22];
    const float* lnPoG  = (const float*)d_in[23];
    const float* lnPoB  = (const float*)d_in[24];
    const float* lnFfG  = (const float*)d_in[25];
    const float* lnFfB  = (const float*)d_in[26];
    float* out = (float*)d_out;

    float *qkv, *cd, *qkvb;
    __half *whi, *wlo, *ah, *fh, *hnh;
    int *degs, *degd, *fill;
    cudaGetSymbolAddress((void**)&hnh,  g_hnh);
    cudaGetSymbolAddress((void**)&qkv,  g_qkv);
    cudaGetSymbolAddress((void**)&cd,   g_cd);
    cudaGetSymbolAddress((void**)&qkvb, g_qkvb);
    cudaGetSymbolAddress((void**)&degs, g_degs);
    cudaGetSymbolAddress((void**)&degd, g_degd);
    cudaGetSymbolAddress((void**)&fill, g_fill);
    cudaGetSymbolAddress((void**)&whi,  g_whi);
    cudaGetSymbolAddress((void**)&wlo,  g_wlo);
    cudaGetSymbolAddress((void**)&ah,   g_ah);
    cudaGetSymbolAddress((void**)&fh,   g_fh);

    cudaFuncSetAttribute(gemm_mma, cudaFuncAttributeMaxDynamicSharedMemorySize, GSMEM);

    const dim3 g256(2, 196, 2);
    const dim3 g768(6, 196, 2);
    const dim3 g512(4, 196, 2);
    const int NB = (NTOT + 255) / 256;   // 196
    const int LNB = NTOT / 8;            // 6250

    // weights + bias + degrees + CSR
    k_wconv_all<<<WCVT_TOTAL/256, 256>>>(preW, postW, qW, kW, vW, oW, fW1, fW2);
    k_qkvb<<<(T_*768 + 255)/256, 256>>>(qB, kB, vB);
    cudaMemsetAsync(degs, 0, sizeof(int) * T_ * NP);
    cudaMemsetAsync(degd, 0, sizeof(int) * T_ * NP);
    cudaMemsetAsync(fill, 0, sizeof(int) * NTOT);
    k_deg<<<(E2 + 255)/256, 256>>>(es, ed);
    k_degnorm<<<(NP + 255)/256, 256>>>();
    k_scan1<<<NB, 256>>>();
    k_scan2<<<1, 256>>>();
    k_scan3<<<NB, 256>>>();
    k_fill<<<(E2 + 255)/256, 256>>>(ed);

    // ---- conv1 ----
    k_lnh<<<LNB, 256>>>(h, lnPreG, lnPreB, hnh);
    k_conv_gather<<<NTOT, 64>>>(es);
    gemm_mma<<<g256, 256, GSMEM>>>(ah, whi+WOFF_PRE, wlo+WOFF_PRE, preB, cd, h, out,
                                   nullptr, NP, HID_, HID_, 1, 0);

    // ---- attention ----
    k_lnh<<<LNB, 256>>>(out, lnAtG, lnAtB, ah);
    gemm_mma<<<g768, 256, GSMEM>>>(ah, whi+WOFF_QKV, wlo+WOFF_QKV, qkvb, nullptr, nullptr,
                                   qkv, nullptr, NP, HID_, 768, 0, 0);
    k_attn<<<NTOT, 64>>>(qkv, es);
    gemm_mma<<<g256, 256, GSMEM>>>(ah, whi+WOFF_O, wlo+WOFF_O, oB, nullptr, out, out,
                                   nullptr, NP, HID_, HID_, 0, 0);

    // ---- conv2 ----
    k_lnh<<<LNB, 256>>>(out, lnPoG, lnPoB, hnh);
    k_conv_gather<<<NTOT, 64>>>(es);
    gemm_mma<<<g256, 256, GSMEM>>>(ah, whi+WOFF_POST, wlo+WOFF_POST, postB, cd, out, out,
                                   nullptr, NP, HID_, HID_, 1, 0);

    // ---- FFN ----
    k_lnh<<<LNB, 256>>>(out, lnFfG, lnFfB, ah);
    gemm_mma<<<g512, 256, GSMEM>>>(ah, whi+WOFF_F1, wlo+WOFF_F1, fB1, nullptr, nullptr,
                                   nullptr, fh, NP, HID_, 512, 0, 1);
    gemm_mma<<<g256, 256, GSMEM>>>(fh, whi+WOFF_F2, wlo+WOFF_F2, fB2, nullptr, out, out,
                                   nullptr, NP, 512, HID_, 0, 0);
}

// round 14
// speedup vs baseline: 1.0741x; 1.0149x over previous
#include <cuda_runtime.h>
#include <cuda_fp16.h>
#include <math.h>

#define T_   2
#define NP   25000
#define EP   200000
#define HID_ 256
#define NTOT (T_*NP)
#define E2   (2*EP)

// ---------------- scratch (static __device__ — no allocations) ----------------
__device__ __half g_hnh[(size_t)T_*NP*HID_];      // fp16 LN out (conv paths)
__device__ float  g_qkv[(size_t)NTOT*768];        // fp32 q|k|v per node
__device__ float  g_sc [(size_t)E2*8];            // ex values (CSR order)
__device__ float  g_cs [T_*NP];
__device__ float  g_cd [T_*NP];
__device__ float  g_qkvb[T_*768];
__device__ int    g_degs[T_*NP];
__device__ int    g_degd[T_*NP];
__device__ int    g_bsum[256];
// CSR by global dst node
__device__ int    g_off [NTOT + 1];
__device__ int    g_fill[NTOT];
__device__ int    g_csr [E2];
// fp16 A operands
__device__ __half g_ah[(size_t)NTOT*HID_];
__device__ __half g_fh[(size_t)NTOT*512];
// split weights, fp16 hi/lo, layout [matrix][t][N][K]
#define WCVT_TOTAL 1310720
__device__ __half g_whi[WCVT_TOTAL];
__device__ __half g_wlo[WCVT_TOTAL];
#define WOFF_PRE  0
#define WOFF_POST 131072
#define WOFF_QKV  262144
#define WOFF_O    655360
#define WOFF_F1   786432
#define WOFF_F2   1048576

// ---------------- mma / async helpers ----------------
__device__ __forceinline__ unsigned smem_u32(const void* p) {
    unsigned a;
    asm("{ .reg .u64 t; cvta.to.shared.u64 t, %1; cvt.u32.u64 %0, t; }" : "=r"(a) : "l"(p));
    return a;
}
#define LDM4(r, a) \
    asm volatile("ldmatrix.sync.aligned.m8n8.x4.shared.b16 {%0,%1,%2,%3}, [%4];" \
        : "=r"((r)[0]),"=r"((r)[1]),"=r"((r)[2]),"=r"((r)[3]) : "r"(a))
#define MMA_F16(c, a, b0, b1) \
    asm volatile("mma.sync.aligned.m16n8k16.row.col.f32.f16.f16.f32 " \
        "{%0,%1,%2,%3}, {%4,%5,%6,%7}, {%8,%9}, {%0,%1,%2,%3};" \
        : "+f"((c)[0]),"+f"((c)[1]),"+f"((c)[2]),"+f"((c)[3]) \
        : "r"((a)[0]),"r"((a)[1]),"r"((a)[2]),"r"((a)[3]), "r"(b0),"r"(b1))
#define CP16(dst, src) \
    asm volatile("cp.async.cg.shared.global [%0], [%1], 16;" :: "r"(dst), "l"(src) : "memory")
#define CP_COMMIT() asm volatile("cp.async.commit_group;" ::: "memory")
#define CP_WAIT0()  asm volatile("cp.async.wait_group 0;" ::: "memory")

__device__ __forceinline__ void store_h4(__half* dst, float4 v) {
    __half2 p0 = __floats2half2_rn(v.x, v.y);
    __half2 p1 = __floats2half2_rn(v.z, v.w);
    uint2 u;
    u.x = *(unsigned*)&p0; u.y = *(unsigned*)&p1;
    *(uint2*)dst = u;
}
__device__ __forceinline__ float4 load_h4(const __half* src) {
    uint2 u = *(const uint2*)src;
    __half2 p0 = *(__half2*)&u.x;
    __half2 p1 = *(__half2*)&u.y;
    float2 f0 = __half22float2(p0);
    float2 f1 = __half22float2(p1);
    return make_float4(f0.x, f0.y, f1.x, f1.y);
}
__device__ __forceinline__ float warp_sum(float v) {
    #pragma unroll
    for (int o = 16; o; o >>= 1) v += __shfl_xor_sync(0xffffffffu, v, o);
    return v;
}

// ---------------- degree + CSR build ----------------
__global__ void k_deg(const int* __restrict__ es, const int* __restrict__ ed) {
    int gid = blockIdx.x * blockDim.x + threadIdx.x;
    if (gid >= E2) return;
    int et = gid / EP;
    atomicAdd(&g_degs[et*NP + es[gid]], 1);
    atomicAdd(&g_degd[et*NP + ed[gid]], 1);
}

__global__ void k_degnorm() {
    int n = blockIdx.x * blockDim.x + threadIdx.x;
    if (n >= NP) return;
    #pragma unroll
    for (int et = 0; et < 2; et++) {
        g_cs[et*NP + n]       = rsqrtf((float)max(g_degs[et*NP + n], 1));
        g_cd[(1-et)*NP + n]   = rsqrtf((float)max(g_degd[et*NP + n], 1));
    }
}

// ---------------- parallel exclusive scan of in-degrees -> g_off ----------------
__global__ void k_scan1() {
    __shared__ int wsum[8];
    int tid = threadIdx.x, lane = tid & 31, wid = tid >> 5;
    int g = blockIdx.x * 256 + tid;
    int deg = 0;
    if (g < NTOT) {
        int dt = g / NP, n = g - dt * NP;
        deg = g_degd[(1 - dt) * NP + n];
    }
    int x = deg;
    #pragma unroll
    for (int o = 1; o < 32; o <<= 1) { int y = __shfl_up_sync(~0u, x, o); if (lane >= o) x += y; }
    if (lane == 31) wsum[wid] = x;
    __syncthreads();
    if (tid == 0) { int s = 0; for (int i = 0; i < 8; i++) { int t2 = wsum[i]; wsum[i] = s; s += t2; } }
    __syncthreads();
    if (g < NTOT) g_off[g] = wsum[wid] + x - deg;
    if (tid == 255) g_bsum[blockIdx.x] = wsum[7] + x;
}

__global__ void k_scan2() {
    __shared__ int wsum[8];
    int tid = threadIdx.x, lane = tid & 31, wid = tid >> 5;
    int v = (tid < 196) ? g_bsum[tid] : 0;
    int x = v;
    #pragma unroll
    for (int o = 1; o < 32; o <<= 1) { int y = __shfl_up_sync(~0u, x, o); if (lane >= o) x += y; }
    if (lane == 31) wsum[wid] = x;
    __syncthreads();
    if (tid == 0) { int s = 0; for (int i = 0; i < 8; i++) { int t2 = wsum[i]; wsum[i] = s; s += t2; } }
    __syncthreads();
    int excl = wsum[wid] + x - v;
    if (tid < 196) g_bsum[tid] = excl;
    if (tid == 195) g_off[NTOT] = excl + v;
}

__global__ void k_scan3() {
    int g = blockIdx.x * 256 + threadIdx.x;
    if (g < NTOT) g_off[g] += g_bsum[blockIdx.x];
}

__global__ void k_fill(const int* __restrict__ ed) {
    int gid = blockIdx.x * blockDim.x + threadIdx.x;
    if (gid >= E2) return;
    int et = gid / EP;
    int gnode = (1 - et) * NP + ed[gid];
    int pos = g_off[gnode] + atomicAdd(&g_fill[gnode], 1);
    g_csr[pos] = gid;
}

// ---------------- layernorm: warp per node, fp16 out to dst ----------------
__global__ void k_lnh(const float* __restrict__ x, const float* __restrict__ g,
                      const float* __restrict__ b, __half* __restrict__ dst) {
    int gn = blockIdx.x * 8 + (threadIdx.x >> 5);
    int lane = threadIdx.x & 31;
    int t = gn / NP;
    size_t base = (size_t)gn * HID_ + lane * 8;
    float4 v0 = *(const float4*)&x[base];
    float4 v1 = *(const float4*)&x[base + 4];
    float s = v0.x+v0.y+v0.z+v0.w + v1.x+v1.y+v1.z+v1.w;
    float mu = warp_sum(s) * (1.0f / HID_);
    float d0x=v0.x-mu, d0y=v0.y-mu, d0z=v0.z-mu, d0w=v0.w-mu;
    float d1x=v1.x-mu, d1y=v1.y-mu, d1z=v1.z-mu, d1w=v1.w-mu;
    float ss = d0x*d0x+d0y*d0y+d0z*d0z+d0w*d0w + d1x*d1x+d1y*d1y+d1z*d1z+d1w*d1w;
    float rstd = rsqrtf(warp_sum(ss) * (1.0f / HID_) + 1e-5f);
    size_t pb = (size_t)t * HID_ + lane * 8;
    float4 g0 = *(const float4*)&g[pb],  g1 = *(const float4*)&g[pb + 4];
    float4 b0 = *(const float4*)&b[pb],  b1 = *(const float4*)&b[pb + 4];
    float4 o0, o1;
    o0.x = d0x*rstd*g0.x + b0.x; o0.y = d0y*rstd*g0.y + b0.y;
    o0.z = d0z*rstd*g0.z + b0.z; o0.w = d0w*rstd*g0.w + b0.w;
    o1.x = d1x*rstd*g1.x + b1.x; o1.y = d1y*rstd*g1.y + b1.y;
    o1.z = d1z*rstd*g1.z + b1.z; o1.w = d1w*rstd*g1.w + b1.w;
    store_h4(&dst[base],     o0);
    store_h4(&dst[base + 4], o1);
}

// ---------------- conv aggregation: CSR gather (fp16 rows), fp16 out ----------------
__global__ void __launch_bounds__(64) k_conv_gather(const int* __restrict__ es) {
    int gnode = blockIdx.x;
    int tid = threadIdx.x;
    int off = g_off[gnode], end = g_off[gnode + 1];
    int dt = gnode / NP;
    int et = 1 - dt;
    float4 acc = make_float4(0.f, 0.f, 0.f, 0.f);
    for (int i = off; i < end; i++) {
        int eid = g_csr[i];
        int src = es[eid];
        float w = g_cs[et*NP + src];
        float4 hv = load_h4(&g_hnh[((size_t)et*NP + src)*HID_ + tid*4]);
        acc.x += hv.x*w; acc.y += hv.y*w; acc.z += hv.z*w; acc.w += hv.w*w;
    }
    store_h4(&g_ah[(size_t)gnode*HID_ + tid*4], acc);
}

// ---------------- fused attention: score+exp+den+gather, fp16 out ----------------
// qkv layout: [node][ q(0:256) | k(256:512) | v(512:768) ] fp32
#define ECACHE 160
__global__ void __launch_bounds__(64) k_attn(const float* __restrict__ qkv,
                                             const int* __restrict__ es) {
    __shared__ float sq[HID_];
    __shared__ float sden[2][8];
    __shared__ int ssrc[ECACHE];
    int gnode = blockIdx.x, tid = threadIdx.x, lane = tid & 31, wid = tid >> 5;
    int off = g_off[gnode], deg = g_off[gnode + 1] - off;

    *(float4*)&sq[tid*4] = *(const float4*)&qkv[(size_t)gnode*768 + tid*4];
    int ncache = (deg < ECACHE) ? deg : ECACHE;
    for (int i = tid; i < ncache; i += 64) {
        int eid = g_csr[off + i];
        int et = eid / EP;
        ssrc[i] = es[eid] + (et ? NP : 0);
    }
    __syncthreads();

    float denAcc = 0.f;
    for (int i = wid; i < deg; i += 2) {
        int sg;
        if (i < ECACHE) sg = ssrc[i];
        else { int eid = g_csr[off + i]; int et = eid / EP; sg = es[eid] + (et ? NP : 0); }
        const float* kv = &qkv[(size_t)sg * 768 + 256];
        float myex = 0.f;
        #pragma unroll
        for (int hh = 0; hh < 8; hh++) {
            float p = sq[hh*32 + lane] * kv[hh*32 + lane];
            p = warp_sum(p);
            float s = fminf(fmaxf(p * 0.17677669529663687f, -5.0f), 5.0f);
            float ex = expf(s);   // s in [-5,5]: no overflow; max-shift cancels exactly
            if (lane == hh) myex = ex;
        }
        if (lane < 8) {
            g_sc[(size_t)(off + i)*8 + lane] = myex;
            denAcc += myex;
        }
    }
    if (lane < 8) sden[wid][lane] = denAcc;
    __syncthreads();

    int hh = tid >> 3;
    float den = sden[0][hh] + sden[1][hh];
    float rden = (den > 0.f) ? 1.0f / den : 0.f;
    float4 acc = make_float4(0.f, 0.f, 0.f, 0.f);
    for (int i = 0; i < deg; i++) {
        int sg;
        if (i < ECACHE) sg = ssrc[i];
        else { int eid = g_csr[off + i]; int et = eid / EP; sg = es[eid] + (et ? NP : 0); }
        float alpha = g_sc[(size_t)(off + i)*8 + hh] * rden;
        const float4 vv = *(const float4*)&qkv[(size_t)sg*768 + 512 + tid*4];
        acc.x += vv.x*alpha; acc.y += vv.y*alpha; acc.z += vv.z*alpha; acc.w += vv.w*alpha;
    }
    store_h4(&g_ah[(size_t)gnode*HID_ + tid*4], acc);
}

// ---------------- all-weights split to fp16 hi/lo (one launch) ----------------
__global__ void k_wconv_all(const float* __restrict__ preW, const float* __restrict__ postW,
                            const float* __restrict__ qW, const float* __restrict__ kW,
                            const float* __restrict__ vW, const float* __restrict__ oW,
                            const float* __restrict__ f1W, const float* __restrict__ f2W) {
    int gid = blockIdx.x * 256 + threadIdx.x;
    if (gid >= WCVT_TOTAL) return;
    float x;
    if (gid < 262144) {                       // PRE, POST: [t][256][256]
        const float* W = (gid < 131072) ? preW : postW;
        int loc = gid & 131071;
        int t = loc >> 16, o = loc & 65535;
        int n = o >> 8, kk = o & 255;
        x = W[t*65536 + kk*256 + n];
    } else if (gid < 655360) {                // QKV: [t][768][256]
        int loc = gid - 262144;
        int t = loc / 196608, r = loc % 196608;
        int n7 = r >> 8, kk = r & 255;
        const float* W; int n;
        if (n7 < 256)      { W = qW; n = n7; }
        else if (n7 < 512) { W = kW; n = n7 - 256; }
        else               { W = vW; n = n7 - 512; }
        x = W[t*65536 + kk*256 + n];
    } else if (gid < 786432) {                // O: [t][256][256]
        int loc = gid - 655360;
        int t = loc >> 16, o = loc & 65535;
        int n = o >> 8, kk = o & 255;
        x = oW[t*65536 + kk*256 + n];
    } else if (gid < 1048576) {               // F1: [t][512][256]
        int loc = gid - 786432;
        int t = loc >> 17, o = loc & 131071;
        int n = o >> 8, kk = o & 255;
        x = f1W[t*131072 + kk*512 + n];
    } else {                                  // F2: [t][256][512]
        int loc = gid - 1048576;
        int t = loc >> 17, o = loc & 131071;
        int n = o >> 9, kk = o & 511;
        x = f2W[t*131072 + kk*256 + n];
    }
    __half h = __float2half_rn(x);
    g_whi[gid] = h;
    g_wlo[gid] = __float2half_rn(x - __half2float(h));
}

__global__ void k_qkvb(const float* __restrict__ qB, const float* __restrict__ kB,
                       const float* __restrict__ vB) {
    int i = blockIdx.x * 256 + threadIdx.x;
    if (i >= T_ * 768) return;
    int t = i / 768, c = i % 768;
    g_qkvb[i] = (c < 256) ? qB[t*256 + c] : (c < 512) ? kB[t*256 + c - 256] : vB[t*256 + c - 512];
}

// ---------------- fp16 tensor GEMM: D = A*(Bhi+Blo), 2-stage cp.async ----------------
// A fp16 [t][M][K]; B split fp16 hi/lo [t][N][K].
// CTA 128x128, 8 warps (4m x 2n), K-chunk 32. Single barrier per iteration:
// the top (post-wait) __syncthreads alone orders stage reuse — a prefetch into
// stage s is issued only after ALL warps passed the barrier following the
// completion of stage s's compute iteration.
#define PAD 40
#define ST_A   (128*PAD)
#define ST_ALL (3*128*PAD)
#define GSMEM  (2*ST_ALL*2)

__global__ void __launch_bounds__(256, 2) gemm_mma(
    const __half* __restrict__ A_g,
    const __half* __restrict__ Bhi_g, const __half* __restrict__ Blo_g,
    const float* __restrict__ bias, const float* __restrict__ rowscale,
    const float* __restrict__ resid, float* __restrict__ C,
    __half* __restrict__ Ch,
    int M, int K, int N, int wswap, int dogelu)
{
    extern __shared__ __half smem[];

    int tid = threadIdx.x;
    int warp = tid >> 5, lane = tid & 31;
    int wm = warp & 3, wn = warp >> 2;
    int t = blockIdx.z;
    int wi = wswap ? (1 - t) : t;

    A_g   += (size_t)t  * M * K;
    Bhi_g += (size_t)wi * K * N;
    Blo_g += (size_t)wi * K * N;
    bias  += (size_t)wi * N;
    const float* rs = rowscale ? rowscale + (size_t)t * M : nullptr;
    const float* rd = resid ? resid + (size_t)t * M * N : nullptr;
    C  += (size_t)t * M * N;
    if (Ch) Ch += (size_t)t * M * N;

    int m0 = blockIdx.y * 128, n0 = blockIdx.x * 128;

    float acc[2][8][4];
    #pragma unroll
    for (int i = 0; i < 2; i++)
        #pragma unroll
        for (int j = 0; j < 8; j++)
            #pragma unroll
            for (int l = 0; l < 4; l++) acc[i][j][l] = 0.f;

    int lrow = lane & 7, lsel = lane >> 3;
    int a_r = (lsel & 1) * 8 + lrow;
    int a_c = (lsel >> 1) * 8;
    int b_r = (lsel >> 1) * 8 + lrow;
    int b_c = (lsel & 1) * 8;

    unsigned usm = smem_u32(smem);
    int grow = tid >> 2, gseg = tid & 3;
    int nchunks = K >> 5;

    {
        unsigned base = usm;
        #pragma unroll
        for (int i = 0; i < 2; i++) {
            int row = grow + i * 64;
            unsigned loc = 2u * (unsigned)(row * PAD + gseg * 8);
            size_t goa = (size_t)(m0 + row) * K + (gseg << 3);
            size_t gob = (size_t)(n0 + row) * K + (gseg << 3);
            CP16(base + loc,               &A_g[goa]);
            CP16(base + 2u*ST_A + loc,     &Bhi_g[gob]);
            CP16(base + 2u*2*ST_A + loc,   &Blo_g[gob]);
        }
        CP_COMMIT();
    }

    for (int c = 0; c < nchunks; c++) {
        int s = c & 1;
        unsigned base = usm + 2u * (unsigned)(s * ST_ALL);
        unsigned ua = base, ubh = base + 2u*ST_A, ubl = base + 2u*2*ST_A;

        CP_WAIT0();
        __syncthreads();

        if (c + 1 < nchunks) {
            int koff = (c + 1) << 5;
            unsigned nb = usm + 2u * (unsigned)((1 - s) * ST_ALL);
            #pragma unroll
            for (int i = 0; i < 2; i++) {
                int row = grow + i * 64;
                unsigned loc = 2u * (unsigned)(row * PAD + gseg * 8);
                size_t goa = (size_t)(m0 + row) * K + koff + (gseg << 3);
                size_t gob = (size_t)(n0 + row) * K + koff + (gseg << 3);
                CP16(nb + loc,             &A_g[goa]);
                CP16(nb + 2u*ST_A + loc,   &Bhi_g[gob]);
                CP16(nb + 2u*2*ST_A + loc, &Blo_g[gob]);
            }
            CP_COMMIT();
        }

        #pragma unroll
        for (int ks = 0; ks < 2; ks++) {
            int kk = ks * 16;
            unsigned ah[2][4];
            #pragma unroll
            for (int mt = 0; mt < 2; mt++) {
                unsigned off = 2u * (unsigned)((wm*32 + mt*16 + a_r) * PAD + kk + a_c);
                LDM4(ah[mt], ua + off);
            }
            #pragma unroll
            for (int bi = 0; bi < 4; bi++) {
                unsigned off = 2u * (unsigned)((wn*64 + bi*16 + b_r) * PAD + kk + b_c);
                unsigned bh[4], bl[4];
                LDM4(bh, ubh + off);
                LDM4(bl, ubl + off);
                #pragma unroll
                for (int mt = 0; mt < 2; mt++) {
                    #pragma unroll
                    for (int j = 0; j < 2; j++) {
                        float* cc = acc[mt][bi*2 + j];
                        MMA_F16(cc, ah[mt], bh[j*2], bh[j*2+1]);
                        MMA_F16(cc, ah[mt], bl[j*2], bl[j*2+1]);
                    }
                }
            }
        }
        // no trailing __syncthreads: next iteration's post-wait barrier
        // provides the required ordering before stage s is overwritten.
    }

    int g = lane >> 2, tig = lane & 3;
    #pragma unroll
    for (int mt = 0; mt < 2; mt++) {
        #pragma unroll
        for (int nt = 0; nt < 8; nt++) {
            int col = n0 + wn*64 + nt*8 + tig*2;
            float b0 = bias[col], b1 = bias[col+1];
            #pragma unroll
            for (int half = 0; half < 2; half++) {
                int r = m0 + wm*32 + mt*16 + g + half*8;
                if (r >= M) continue;
                float scale = rs ? rs[r] : 1.0f;
                size_t idx = (size_t)r * N + col;
                float2 o;
                o.x = acc[mt][nt][half*2+0] * scale + b0;
                o.y = acc[mt][nt][half*2+1] * scale + b1;
                if (rd) {
                    const float2 rv = *(const float2*)&rd[idx];
                    o.x += rv.x; o.y += rv.y;
                }
                if (dogelu) {
                    o.x = 0.5f*o.x*(1.0f+erff(o.x*0.70710678118654752f));
                    o.y = 0.5f*o.y*(1.0f+erff(o.y*0.70710678118654752f));
                }
                if (Ch) {
                    __half2 p = __floats2half2_rn(o.x, o.y);
                    *(unsigned*)&Ch[idx] = *(unsigned*)&p;
                } else {
                    *(float2*)&C[idx] = o;
                }
            }
        }
    }
}

// ---------------- host orchestration ----------------
extern "C" void kernel_launch(void* const* d_in, const int* in_sizes, int n_in,
                              void* d_out, int out_size) {
    const float* h      = (const float*)d_in[0];
    const int*   es     = (const int*)  d_in[1];
    const int*   ed     = (const int*)  d_in[2];
    const float* preW   = (const float*)d_in[3];
    const float* preB   = (const float*)d_in[4];
    const float* postW  = (const float*)d_in[5];
    const float* postB  = (const float*)d_in[6];
    const float* qW     = (const float*)d_in[7];
    const float* qB     = (const float*)d_in[8];
    const float* kW     = (const float*)d_in[9];
    const float* kB     = (const float*)d_in[10];
    const float* vW     = (const float*)d_in[11];
    const float* vB     = (const float*)d_in[12];
    const float* oW     = (const float*)d_in[13];
    const float* oB     = (const float*)d_in[14];
    const float* fW1    = (const float*)d_in[15];
    const float* fB1    = (const float*)d_in[16];
    const float* fW2    = (const float*)d_in[17];
    const float* fB2    = (const float*)d_in[18];
    const float* lnPreG = (const float*)d_in[19];
    const float* lnPreB = (const float*)d_in[20];
    const float* lnAtG  = (const float*)d_in[21];
    const float* lnAtB  = (const float*)d_in[22];
    const float* lnPoG  = (const float*)d_in[23];
    const float* lnPoB  = (const float*)d_in[24];
    const float* lnFfG  = (const float*)d_in[25];
    const float* lnFfB  = (const float*)d_in[26];
    float* out = (float*)d_out;

    float *qkv, *cd, *qkvb;
    __half *whi, *wlo, *ah, *fh, *hnh;
    int *degs, *degd, *fill;
    cudaGetSymbolAddress((void**)&hnh,  g_hnh);
    cudaGetSymbolAddress((void**)&qkv,  g_qkv);
    cudaGetSymbolAddress((void**)&cd,   g_cd);
    cudaGetSymbolAddress((void**)&qkvb, g_qkvb);
    cudaGetSymbolAddress((void**)&degs, g_degs);
    cudaGetSymbolAddress((void**)&degd, g_degd);
    cudaGetSymbolAddress((void**)&fill, g_fill);
    cudaGetSymbolAddress((void**)&whi,  g_whi);
    cudaGetSymbolAddress((void**)&wlo,  g_wlo);
    cudaGetSymbolAddress((void**)&ah,   g_ah);
    cudaGetSymbolAddress((void**)&fh,   g_fh);

    cudaFuncSetAttribute(gemm_mma, cudaFuncAttributeMaxDynamicSharedMemorySize, GSMEM);

    // side stream + events for captured fork/join (created once; reused —
    // identical GPU work every call)
    static cudaStream_t s1 = nullptr;
    static cudaEvent_t evF = nullptr, evJ = nullptr;
    if (!s1) {
        cudaStreamCreateWithFlags(&s1, cudaStreamNonBlocking);
        cudaEventCreateWithFlags(&evF, cudaEventDisableTiming);
        cudaEventCreateWithFlags(&evJ, cudaEventDisableTiming);
    }

    const dim3 g256(2, 196, 2);
    const dim3 g768(6, 196, 2);
    const dim3 g512(4, 196, 2);
    const int NB = (NTOT + 255) / 256;   // 196
    const int LNB = NTOT / 8;            // 6250

    // ---- fork: CSR/degree chain on s1, weight split + LN1 on main ----
    cudaEventRecord(evF, 0);
    cudaStreamWaitEvent(s1, evF, 0);

    cudaMemsetAsync(degs, 0, sizeof(int) * T_ * NP, s1);
    cudaMemsetAsync(degd, 0, sizeof(int) * T_ * NP, s1);
    cudaMemsetAsync(fill, 0, sizeof(int) * NTOT, s1);
    k_deg<<<(E2 + 255)/256, 256, 0, s1>>>(es, ed);
    k_degnorm<<<(NP + 255)/256, 256, 0, s1>>>();
    k_scan1<<<NB, 256, 0, s1>>>();
    k_scan2<<<1, 256, 0, s1>>>();
    k_scan3<<<NB, 256, 0, s1>>>();
    k_fill<<<(E2 + 255)/256, 256, 0, s1>>>(ed);
    cudaEventRecord(evJ, s1);

    k_wconv_all<<<WCVT_TOTAL/256, 256>>>(preW, postW, qW, kW, vW, oW, fW1, fW2);
    k_qkvb<<<(T_*768 + 255)/256, 256>>>(qB, kB, vB);
    k_lnh<<<LNB, 256>>>(h, lnPreG, lnPreB, hnh);

    cudaStreamWaitEvent(0, evJ, 0);   // join before CSR consumers

    // ---- conv1 ----
    k_conv_gather<<<NTOT, 64>>>(es);
    gemm_mma<<<g256, 256, GSMEM>>>(ah, whi+WOFF_PRE, wlo+WOFF_PRE, preB, cd, h, out,
                                   nullptr, NP, HID_, HID_, 1, 0);

    // ---- attention ----
    k_lnh<<<LNB, 256>>>(out, lnAtG, lnAtB, ah);
    gemm_mma<<<g768, 256, GSMEM>>>(ah, whi+WOFF_QKV, wlo+WOFF_QKV, qkvb, nullptr, nullptr,
                                   qkv, nullptr, NP, HID_, 768, 0, 0);
    k_attn<<<NTOT, 64>>>(qkv, es);
    gemm_mma<<<g256, 256, GSMEM>>>(ah, whi+WOFF_O, wlo+WOFF_O, oB, nullptr, out, out,
                                   nullptr, NP, HID_, HID_, 0, 0);

    // ---- conv2 ----
    k_lnh<<<LNB, 256>>>(out, lnPoG, lnPoB, hnh);
    k_conv_gather<<<NTOT, 64>>>(es);
    gemm_mma<<<g256, 256, GSMEM>>>(ah, whi+WOFF_POST, wlo+WOFF_POST, postB, cd, out, out,
                                   nullptr, NP, HID_, HID_, 1, 0);

    // ---- FFN ----
    k_lnh<<<LNB, 256>>>(out, lnFfG, lnFfB, ah);
    gemm_mma<<<g512, 256, GSMEM>>>(ah, whi+WOFF_F1, wlo+WOFF_F1, fB1, nullptr, nullptr,
                                   nullptr, fh, NP, HID_, 512, 0, 1);
    gemm_mma<<<g256, 256, GSMEM>>>(fh, whi+WOFF_F2, wlo+WOFF_F2, fB2, nullptr, out, out,
                                   nullptr, NP, 512, HID_, 0, 0);
}

// round 15
// speedup vs baseline: 1.1187x; 1.0415x over previous
#include <cuda_runtime.h>
#include <cuda_fp16.h>
#include <math.h>

#define T_   2
#define NP   25000
#define EP   200000
#define HID_ 256
#define NTOT (T_*NP)
#define E2   (2*EP)

// ---------------- scratch (static __device__ — no allocations) ----------------
__device__ __half g_hnh[(size_t)T_*NP*HID_];      // fp16 LN out (conv paths)
__device__ float  g_qkv[(size_t)NTOT*768];        // fp32 q|k|v per node
__device__ float  g_sc [(size_t)E2*8];            // ex overflow (deg>ECACHE only)
__device__ float  g_cs [T_*NP];
__device__ float  g_cd [T_*NP];
__device__ float  g_qkvb[T_*768];
__device__ int    g_degs[T_*NP];
__device__ int    g_degd[T_*NP];
__device__ int    g_bsum[256];
// CSR by global dst node
__device__ int    g_off [NTOT + 1];
__device__ int    g_fill[NTOT];
__device__ int    g_csr [E2];
// fp16 A operands
__device__ __half g_ah[(size_t)NTOT*HID_];
__device__ __half g_fh[(size_t)NTOT*512];
// split weights, fp16 hi/lo, layout [matrix][t][N][K]
#define WCVT_TOTAL 1310720
__device__ __half g_whi[WCVT_TOTAL];
__device__ __half g_wlo[WCVT_TOTAL];
#define WOFF_PRE  0
#define WOFF_POST 131072
#define WOFF_QKV  262144
#define WOFF_O    655360
#define WOFF_F1   786432
#define WOFF_F2   1048576

// ---------------- mma / async helpers ----------------
__device__ __forceinline__ unsigned smem_u32(const void* p) {
    unsigned a;
    asm("{ .reg .u64 t; cvta.to.shared.u64 t, %1; cvt.u32.u64 %0, t; }" : "=r"(a) : "l"(p));
    return a;
}
#define LDM4(r, a) \
    asm volatile("ldmatrix.sync.aligned.m8n8.x4.shared.b16 {%0,%1,%2,%3}, [%4];" \
        : "=r"((r)[0]),"=r"((r)[1]),"=r"((r)[2]),"=r"((r)[3]) : "r"(a))
#define MMA_F16(c, a, b0, b1) \
    asm volatile("mma.sync.aligned.m16n8k16.row.col.f32.f16.f16.f32 " \
        "{%0,%1,%2,%3}, {%4,%5,%6,%7}, {%8,%9}, {%0,%1,%2,%3};" \
        : "+f"((c)[0]),"+f"((c)[1]),"+f"((c)[2]),"+f"((c)[3]) \
        : "r"((a)[0]),"r"((a)[1]),"r"((a)[2]),"r"((a)[3]), "r"(b0),"r"(b1))
#define CP16(dst, src) \
    asm volatile("cp.async.cg.shared.global [%0], [%1], 16;" :: "r"(dst), "l"(src) : "memory")
#define CP_COMMIT() asm volatile("cp.async.commit_group;" ::: "memory")
#define CP_WAIT0()  asm volatile("cp.async.wait_group 0;" ::: "memory")

__device__ __forceinline__ void store_h4(__half* dst, float4 v) {
    __half2 p0 = __floats2half2_rn(v.x, v.y);
    __half2 p1 = __floats2half2_rn(v.z, v.w);
    uint2 u;
    u.x = *(unsigned*)&p0; u.y = *(unsigned*)&p1;
    *(uint2*)dst = u;
}
__device__ __forceinline__ float4 load_h4(const __half* src) {
    uint2 u = *(const uint2*)src;
    __half2 p0 = *(__half2*)&u.x;
    __half2 p1 = *(__half2*)&u.y;
    float2 f0 = __half22float2(p0);
    float2 f1 = __half22float2(p1);
    return make_float4(f0.x, f0.y, f1.x, f1.y);
}
__device__ __forceinline__ float warp_sum(float v) {
    #pragma unroll
    for (int o = 16; o; o >>= 1) v += __shfl_xor_sync(0xffffffffu, v, o);
    return v;
}

// ---------------- degree + CSR build ----------------
__global__ void k_deg(const int* __restrict__ es, const int* __restrict__ ed) {
    int gid = blockIdx.x * blockDim.x + threadIdx.x;
    if (gid >= E2) return;
    int et = gid / EP;
    atomicAdd(&g_degs[et*NP + es[gid]], 1);
    atomicAdd(&g_degd[et*NP + ed[gid]], 1);
}

__global__ void k_degnorm() {
    int n = blockIdx.x * blockDim.x + threadIdx.x;
    if (n >= NP) return;
    #pragma unroll
    for (int et = 0; et < 2; et++) {
        g_cs[et*NP + n]       = rsqrtf((float)max(g_degs[et*NP + n], 1));
        g_cd[(1-et)*NP + n]   = rsqrtf((float)max(g_degd[et*NP + n], 1));
    }
}

// ---------------- parallel exclusive scan of in-degrees -> g_off ----------------
__global__ void k_scan1() {
    __shared__ int wsum[8];
    int tid = threadIdx.x, lane = tid & 31, wid = tid >> 5;
    int g = blockIdx.x * 256 + tid;
    int deg = 0;
    if (g < NTOT) {
        int dt = g / NP, n = g - dt * NP;
        deg = g_degd[(1 - dt) * NP + n];
    }
    int x = deg;
    #pragma unroll
    for (int o = 1; o < 32; o <<= 1) { int y = __shfl_up_sync(~0u, x, o); if (lane >= o) x += y; }
    if (lane == 31) wsum[wid] = x;
    __syncthreads();
    if (tid == 0) { int s = 0; for (int i = 0; i < 8; i++) { int t2 = wsum[i]; wsum[i] = s; s += t2; } }
    __syncthreads();
    if (g < NTOT) g_off[g] = wsum[wid] + x - deg;
    if (tid == 255) g_bsum[blockIdx.x] = wsum[7] + x;
}

__global__ void k_scan2() {
    __shared__ int wsum[8];
    int tid = threadIdx.x, lane = tid & 31, wid = tid >> 5;
    int v = (tid < 196) ? g_bsum[tid] : 0;
    int x = v;
    #pragma unroll
    for (int o = 1; o < 32; o <<= 1) { int y = __shfl_up_sync(~0u, x, o); if (lane >= o) x += y; }
    if (lane == 31) wsum[wid] = x;
    __syncthreads();
    if (tid == 0) { int s = 0; for (int i = 0; i < 8; i++) { int t2 = wsum[i]; wsum[i] = s; s += t2; } }
    __syncthreads();
    int excl = wsum[wid] + x - v;
    if (tid < 196) g_bsum[tid] = excl;
    if (tid == 195) g_off[NTOT] = excl + v;
}

__global__ void k_scan3() {
    int g = blockIdx.x * 256 + threadIdx.x;
    if (g < NTOT) g_off[g] += g_bsum[blockIdx.x];
}

__global__ void k_fill(const int* __restrict__ ed) {
    int gid = blockIdx.x * blockDim.x + threadIdx.x;
    if (gid >= E2) return;
    int et = gid / EP;
    int gnode = (1 - et) * NP + ed[gid];
    int pos = g_off[gnode] + atomicAdd(&g_fill[gnode], 1);
    g_csr[pos] = gid;
}

// ---------------- layernorm: warp per node, fp16 out to dst ----------------
__global__ void k_lnh(const float* __restrict__ x, const float* __restrict__ g,
                      const float* __restrict__ b, __half* __restrict__ dst) {
    int gn = blockIdx.x * 8 + (threadIdx.x >> 5);
    int lane = threadIdx.x & 31;
    int t = gn / NP;
    size_t base = (size_t)gn * HID_ + lane * 8;
    float4 v0 = *(const float4*)&x[base];
    float4 v1 = *(const float4*)&x[base + 4];
    float s = v0.x+v0.y+v0.z+v0.w + v1.x+v1.y+v1.z+v1.w;
    float mu = warp_sum(s) * (1.0f / HID_);
    float d0x=v0.x-mu, d0y=v0.y-mu, d0z=v0.z-mu, d0w=v0.w-mu;
    float d1x=v1.x-mu, d1y=v1.y-mu, d1z=v1.z-mu, d1w=v1.w-mu;
    float ss = d0x*d0x+d0y*d0y+d0z*d0z+d0w*d0w + d1x*d1x+d1y*d1y+d1z*d1z+d1w*d1w;
    float rstd = rsqrtf(warp_sum(ss) * (1.0f / HID_) + 1e-5f);
    size_t pb = (size_t)t * HID_ + lane * 8;
    float4 g0 = *(const float4*)&g[pb],  g1 = *(const float4*)&g[pb + 4];
    float4 b0 = *(const float4*)&b[pb],  b1 = *(const float4*)&b[pb + 4];
    float4 o0, o1;
    o0.x = d0x*rstd*g0.x + b0.x; o0.y = d0y*rstd*g0.y + b0.y;
    o0.z = d0z*rstd*g0.z + b0.z; o0.w = d0w*rstd*g0.w + b0.w;
    o1.x = d1x*rstd*g1.x + b1.x; o1.y = d1y*rstd*g1.y + b1.y;
    o1.z = d1z*rstd*g1.z + b1.z; o1.w = d1w*rstd*g1.w + b1.w;
    store_h4(&dst[base],     o0);
    store_h4(&dst[base + 4], o1);
}

// ---------------- conv aggregation: CSR gather (fp16 rows), fp16 out ----------------
__global__ void __launch_bounds__(64) k_conv_gather(const int* __restrict__ es) {
    int gnode = blockIdx.x;
    int tid = threadIdx.x;
    int off = g_off[gnode], end = g_off[gnode + 1];
    int dt = gnode / NP;
    int et = 1 - dt;
    float4 acc = make_float4(0.f, 0.f, 0.f, 0.f);
    for (int i = off; i < end; i++) {
        int eid = g_csr[i];
        int src = es[eid];
        float w = g_cs[et*NP + src];
        float4 hv = load_h4(&g_hnh[((size_t)et*NP + src)*HID_ + tid*4]);
        acc.x += hv.x*w; acc.y += hv.y*w; acc.z += hv.z*w; acc.w += hv.w*w;
    }
    store_h4(&g_ah[(size_t)gnode*HID_ + tid*4], acc);
}

// ---------------- fused attention: score+exp+den+gather, fp16 out ----------------
// qkv layout: [node][ q(0:256) | k(256:512) | v(512:768) ] fp32.
// ex values cached in SMEM for the first ECACHE edges (covers ~all nodes,
// Poisson(8) in-degree); overflow edges spill to g_sc.
#define ECACHE 64
__global__ void __launch_bounds__(64) k_attn(const float* __restrict__ qkv,
                                             const int* __restrict__ es) {
    __shared__ float sq[HID_];
    __shared__ float sden[2][8];
    __shared__ float sex[ECACHE * 8];
    __shared__ int ssrc[ECACHE];
    int gnode = blockIdx.x, tid = threadIdx.x, lane = tid & 31, wid = tid >> 5;
    int off = g_off[gnode], deg = g_off[gnode + 1] - off;

    *(float4*)&sq[tid*4] = *(const float4*)&qkv[(size_t)gnode*768 + tid*4];
    int ncache = (deg < ECACHE) ? deg : ECACHE;
    for (int i = tid; i < ncache; i += 64) {
        int eid = g_csr[off + i];
        int et = eid / EP;
        ssrc[i] = es[eid] + (et ? NP : 0);
    }
    __syncthreads();

    float denAcc = 0.f;
    for (int i = wid; i < deg; i += 2) {
        int sg;
        if (i < ECACHE) sg = ssrc[i];
        else { int eid = g_csr[off + i]; int et = eid / EP; sg = es[eid] + (et ? NP : 0); }
        const float* kv = &qkv[(size_t)sg * 768 + 256];
        float myex = 0.f;
        #pragma unroll
        for (int hh = 0; hh < 8; hh++) {
            float p = sq[hh*32 + lane] * kv[hh*32 + lane];
            p = warp_sum(p);
            float s = fminf(fmaxf(p * 0.17677669529663687f, -5.0f), 5.0f);
            float ex = expf(s);   // s in [-5,5]: no overflow; max-shift cancels exactly
            if (lane == hh) myex = ex;
        }
        if (lane < 8) {
            if (i < ECACHE) sex[i*8 + lane] = myex;
            else            g_sc[(size_t)(off + i)*8 + lane] = myex;
            denAcc += myex;
        }
    }
    if (lane < 8) sden[wid][lane] = denAcc;
    __syncthreads();

    int hh = tid >> 3;
    float den = sden[0][hh] + sden[1][hh];
    float rden = (den > 0.f) ? 1.0f / den : 0.f;
    float4 acc = make_float4(0.f, 0.f, 0.f, 0.f);
    for (int i = 0; i < deg; i++) {
        int sg; float ex;
        if (i < ECACHE) { sg = ssrc[i]; ex = sex[i*8 + hh]; }
        else {
            int eid = g_csr[off + i]; int et = eid / EP;
            sg = es[eid] + (et ? NP : 0);
            ex = g_sc[(size_t)(off + i)*8 + hh];
        }
        float alpha = ex * rden;
        const float4 vv = *(const float4*)&qkv[(size_t)sg*768 + 512 + tid*4];
        acc.x += vv.x*alpha; acc.y += vv.y*alpha; acc.z += vv.z*alpha; acc.w += vv.w*alpha;
    }
    store_h4(&g_ah[(size_t)gnode*HID_ + tid*4], acc);
}

// ---------------- all-weights split to fp16 hi/lo (one launch) ----------------
__global__ void k_wconv_all(const float* __restrict__ preW, const float* __restrict__ postW,
                            const float* __restrict__ qW, const float* __restrict__ kW,
                            const float* __restrict__ vW, const float* __restrict__ oW,
                            const float* __restrict__ f1W, const float* __restrict__ f2W) {
    int gid = blockIdx.x * 256 + threadIdx.x;
    if (gid >= WCVT_TOTAL) return;
    float x;
    if (gid < 262144) {                       // PRE, POST: [t][256][256]
        const float* W = (gid < 131072) ? preW : postW;
        int loc = gid & 131071;
        int t = loc >> 16, o = loc & 65535;
        int n = o >> 8, kk = o & 255;
        x = W[t*65536 + kk*256 + n];
    } else if (gid < 655360) {                // QKV: [t][768][256]
        int loc = gid - 262144;
        int t = loc / 196608, r = loc % 196608;
        int n7 = r >> 8, kk = r & 255;
        const float* W; int n;
        if (n7 < 256)      { W = qW; n = n7; }
        else if (n7 < 512) { W = kW; n = n7 - 256; }
        else               { W = vW; n = n7 - 512; }
        x = W[t*65536 + kk*256 + n];
    } else if (gid < 786432) {                // O: [t][256][256]
        int loc = gid - 655360;
        int t = loc >> 16, o = loc & 65535;
        int n = o >> 8, kk = o & 255;
        x = oW[t*65536 + kk*256 + n];
    } else if (gid < 1048576) {               // F1: [t][512][256]
        int loc = gid - 786432;
        int t = loc >> 17, o = loc & 131071;
        int n = o >> 8, kk = o & 255;
        x = f1W[t*131072 + kk*512 + n];
    } else {                                  // F2: [t][256][512]
        int loc = gid - 1048576;
        int t = loc >> 17, o = loc & 131071;
        int n = o >> 9, kk = o & 511;
        x = f2W[t*131072 + kk*256 + n];
    }
    __half h = __float2half_rn(x);
    g_whi[gid] = h;
    g_wlo[gid] = __float2half_rn(x - __half2float(h));
}

__global__ void k_qkvb(const float* __restrict__ qB, const float* __restrict__ kB,
                       const float* __restrict__ vB) {
    int i = blockIdx.x * 256 + threadIdx.x;
    if (i >= T_ * 768) return;
    int t = i / 768, c = i % 768;
    g_qkvb[i] = (c < 256) ? qB[t*256 + c] : (c < 512) ? kB[t*256 + c - 256] : vB[t*256 + c - 512];
}

// ---------------- fp16 tensor GEMM: D = A*(Bhi+Blo), 2-stage cp.async, K-chunk 64 ----------------
// A fp16 [t][M][K]; B split fp16 hi/lo [t][N][K].
// CTA 128x128, 8 warps (4m x 2n). Single barrier per chunk iteration.
#define PAD 72
#define ST_A   (128*PAD)
#define ST_ALL (3*128*PAD)
#define GSMEM  (2*ST_ALL*2)

__global__ void __launch_bounds__(256, 2) gemm_mma(
    const __half* __restrict__ A_g,
    const __half* __restrict__ Bhi_g, const __half* __restrict__ Blo_g,
    const float* __restrict__ bias, const float* __restrict__ rowscale,
    const float* __restrict__ resid, float* __restrict__ C,
    __half* __restrict__ Ch,
    int M, int K, int N, int wswap, int dogelu)
{
    extern __shared__ __half smem[];

    int tid = threadIdx.x;
    int warp = tid >> 5, lane = tid & 31;
    int wm = warp & 3, wn = warp >> 2;
    int t = blockIdx.z;
    int wi = wswap ? (1 - t) : t;

    A_g   += (size_t)t  * M * K;
    Bhi_g += (size_t)wi * K * N;
    Blo_g += (size_t)wi * K * N;
    bias  += (size_t)wi * N;
    const float* rs = rowscale ? rowscale + (size_t)t * M : nullptr;
    const float* rd = resid ? resid + (size_t)t * M * N : nullptr;
    C  += (size_t)t * M * N;
    if (Ch) Ch += (size_t)t * M * N;

    int m0 = blockIdx.y * 128, n0 = blockIdx.x * 128;

    float acc[2][8][4];
    #pragma unroll
    for (int i = 0; i < 2; i++)
        #pragma unroll
        for (int j = 0; j < 8; j++)
            #pragma unroll
            for (int l = 0; l < 4; l++) acc[i][j][l] = 0.f;

    int lrow = lane & 7, lsel = lane >> 3;
    int a_r = (lsel & 1) * 8 + lrow;
    int a_c = (lsel >> 1) * 8;
    int b_r = (lsel >> 1) * 8 + lrow;
    int b_c = (lsel & 1) * 8;

    unsigned usm = smem_u32(smem);
    int grow = tid >> 3, gseg = tid & 7;    // chunk row = 64 elts = 8x16B segs
    int nchunks = K >> 6;

    // issue loads for chunk cc into stage st (4 rows per thread per buffer)
    {
        unsigned base = usm;
        #pragma unroll
        for (int i = 0; i < 4; i++) {
            int row = grow + i * 32;
            unsigned loc = 2u * (unsigned)(row * PAD + gseg * 8);
            size_t goa = (size_t)(m0 + row) * K + (gseg << 3);
            size_t gob = (size_t)(n0 + row) * K + (gseg << 3);
            CP16(base + loc,               &A_g[goa]);
            CP16(base + 2u*ST_A + loc,     &Bhi_g[gob]);
            CP16(base + 2u*2*ST_A + loc,   &Blo_g[gob]);
        }
        CP_COMMIT();
    }

    for (int c = 0; c < nchunks; c++) {
        int s = c & 1;
        unsigned base = usm + 2u * (unsigned)(s * ST_ALL);
        unsigned ua = base, ubh = base + 2u*ST_A, ubl = base + 2u*2*ST_A;

        CP_WAIT0();
        __syncthreads();

        if (c + 1 < nchunks) {
            int koff = (c + 1) << 6;
            unsigned nb = usm + 2u * (unsigned)((1 - s) * ST_ALL);
            #pragma unroll
            for (int i = 0; i < 4; i++) {
                int row = grow + i * 32;
                unsigned loc = 2u * (unsigned)(row * PAD + gseg * 8);
                size_t goa = (size_t)(m0 + row) * K + koff + (gseg << 3);
                size_t gob = (size_t)(n0 + row) * K + koff + (gseg << 3);
                CP16(nb + loc,             &A_g[goa]);
                CP16(nb + 2u*ST_A + loc,   &Bhi_g[gob]);
                CP16(nb + 2u*2*ST_A + loc, &Blo_g[gob]);
            }
            CP_COMMIT();
        }

        #pragma unroll
        for (int ks = 0; ks < 4; ks++) {
            int kk = ks * 16;
            unsigned ah[2][4];
            #pragma unroll
            for (int mt = 0; mt < 2; mt++) {
                unsigned off = 2u * (unsigned)((wm*32 + mt*16 + a_r) * PAD + kk + a_c);
                LDM4(ah[mt], ua + off);
            }
            #pragma unroll
            for (int bi = 0; bi < 4; bi++) {
                unsigned off = 2u * (unsigned)((wn*64 + bi*16 + b_r) * PAD + kk + b_c);
                unsigned bh[4], bl[4];
                LDM4(bh, ubh + off);
                LDM4(bl, ubl + off);
                #pragma unroll
                for (int mt = 0; mt < 2; mt++) {
                    #pragma unroll
                    for (int j = 0; j < 2; j++) {
                        float* cc = acc[mt][bi*2 + j];
                        MMA_F16(cc, ah[mt], bh[j*2], bh[j*2+1]);
                        MMA_F16(cc, ah[mt], bl[j*2], bl[j*2+1]);
                    }
                }
            }
        }
        // no trailing __syncthreads: next iteration's post-wait barrier
        // orders stage reuse.
    }

    int g = lane >> 2, tig = lane & 3;
    #pragma unroll
    for (int mt = 0; mt < 2; mt++) {
        #pragma unroll
        for (int nt = 0; nt < 8; nt++) {
            int col = n0 + wn*64 + nt*8 + tig*2;
            float b0 = bias[col], b1 = bias[col+1];
            #pragma unroll
            for (int half = 0; half < 2; half++) {
                int r = m0 + wm*32 + mt*16 + g + half*8;
                if (r >= M) continue;
                float scale = rs ? rs[r] : 1.0f;
                size_t idx = (size_t)r * N + col;
                float2 o;
                o.x = acc[mt][nt][half*2+0] * scale + b0;
                o.y = acc[mt][nt][half*2+1] * scale + b1;
                if (rd) {
                    const float2 rv = *(const float2*)&rd[idx];
                    o.x += rv.x; o.y += rv.y;
                }
                if (dogelu) {
                    o.x = 0.5f*o.x*(1.0f+erff(o.x*0.70710678118654752f));
                    o.y = 0.5f*o.y*(1.0f+erff(o.y*0.70710678118654752f));
                }
                if (Ch) {
                    __half2 p = __floats2half2_rn(o.x, o.y);
                    *(unsigned*)&Ch[idx] = *(unsigned*)&p;
                } else {
                    *(float2*)&C[idx] = o;
                }
            }
        }
    }
}

// ---------------- host orchestration ----------------
extern "C" void kernel_launch(void* const* d_in, const int* in_sizes, int n_in,
                              void* d_out, int out_size) {
    const float* h      = (const float*)d_in[0];
    const int*   es     = (const int*)  d_in[1];
    const int*   ed     = (const int*)  d_in[2];
    const float* preW   = (const float*)d_in[3];
    const float* preB   = (const float*)d_in[4];
    const float* postW  = (const float*)d_in[5];
    const float* postB  = (const float*)d_in[6];
    const float* qW     = (const float*)d_in[7];
    const float* qB     = (const float*)d_in[8];
    const float* kW     = (const float*)d_in[9];
    const float* kB     = (const float*)d_in[10];
    const float* vW     = (const float*)d_in[11];
    const float* vB     = (const float*)d_in[12];
    const float* oW     = (const float*)d_in[13];
    const float* oB     = (const float*)d_in[14];
    const float* fW1    = (const float*)d_in[15];
    const float* fB1    = (const float*)d_in[16];
    const float* fW2    = (const float*)d_in[17];
    const float* fB2    = (const float*)d_in[18];
    const float* lnPreG = (const float*)d_in[19];
    const float* lnPreB = (const float*)d_in[20];
    const float* lnAtG  = (const float*)d_in[21];
    const float* lnAtB  = (const float*)d_in[22];
    const float* lnPoG  = (const float*)d_in[23];
    const float* lnPoB  = (const float*)d_in[24];
    const float* lnFfG  = (const float*)d_in[25];
    const float* lnFfB  = (const float*)d_in[26];
    float* out = (float*)d_out;

    float *qkv, *cd, *qkvb;
    __half *whi, *wlo, *ah, *fh, *hnh;
    int *degs, *degd, *fill;
    cudaGetSymbolAddress((void**)&hnh,  g_hnh);
    cudaGetSymbolAddress((void**)&qkv,  g_qkv);
    cudaGetSymbolAddress((void**)&cd,   g_cd);
    cudaGetSymbolAddress((void**)&qkvb, g_qkvb);
    cudaGetSymbolAddress((void**)&degs, g_degs);
    cudaGetSymbolAddress((void**)&degd, g_degd);
    cudaGetSymbolAddress((void**)&fill, g_fill);
    cudaGetSymbolAddress((void**)&whi,  g_whi);
    cudaGetSymbolAddress((void**)&wlo,  g_wlo);
    cudaGetSymbolAddress((void**)&ah,   g_ah);
    cudaGetSymbolAddress((void**)&fh,   g_fh);

    cudaFuncSetAttribute(gemm_mma, cudaFuncAttributeMaxDynamicSharedMemorySize, GSMEM);

    static cudaStream_t s1 = nullptr;
    static cudaEvent_t evF = nullptr, evJ = nullptr;
    if (!s1) {
        cudaStreamCreateWithFlags(&s1, cudaStreamNonBlocking);
        cudaEventCreateWithFlags(&evF, cudaEventDisableTiming);
        cudaEventCreateWithFlags(&evJ, cudaEventDisableTiming);
    }

    const dim3 g256(2, 196, 2);
    const dim3 g768(6, 196, 2);
    const dim3 g512(4, 196, 2);
    const int NB = (NTOT + 255) / 256;   // 196
    const int LNB = NTOT / 8;            // 6250

    // ---- fork: CSR/degree chain on s1, weight split + LN1 on main ----
    cudaEventRecord(evF, 0);
    cudaStreamWaitEvent(s1, evF, 0);

    cudaMemsetAsync(degs, 0, sizeof(int) * T_ * NP, s1);
    cudaMemsetAsync(degd, 0, sizeof(int) * T_ * NP, s1);
    cudaMemsetAsync(fill, 0, sizeof(int) * NTOT, s1);
    k_deg<<<(E2 + 255)/256, 256, 0, s1>>>(es, ed);
    k_degnorm<<<(NP + 255)/256, 256, 0, s1>>>();
    k_scan1<<<NB, 256, 0, s1>>>();
    k_scan2<<<1, 256, 0, s1>>>();
    k_scan3<<<NB, 256, 0, s1>>>();
    k_fill<<<(E2 + 255)/256, 256, 0, s1>>>(ed);
    cudaEventRecord(evJ, s1);

    k_wconv_all<<<WCVT_TOTAL/256, 256>>>(preW, postW, qW, kW, vW, oW, fW1, fW2);
    k_qkvb<<<(T_*768 + 255)/256, 256>>>(qB, kB, vB);
    k_lnh<<<LNB, 256>>>(h, lnPreG, lnPreB, hnh);

    cudaStreamWaitEvent(0, evJ, 0);   // join before CSR consumers

    // ---- conv1 ----
    k_conv_gather<<<NTOT, 64>>>(es);
    gemm_mma<<<g256, 256, GSMEM>>>(ah, whi+WOFF_PRE, wlo+WOFF_PRE, preB, cd, h, out,
                                   nullptr, NP, HID_, HID_, 1, 0);

    // ---- attention ----
    k_lnh<<<LNB, 256>>>(out, lnAtG, lnAtB, ah);
    gemm_mma<<<g768, 256, GSMEM>>>(ah, whi+WOFF_QKV, wlo+WOFF_QKV, qkvb, nullptr, nullptr,
                                   qkv, nullptr, NP, HID_, 768, 0, 0);
    k_attn<<<NTOT, 64>>>(qkv, es);
    gemm_mma<<<g256, 256, GSMEM>>>(ah, whi+WOFF_O, wlo+WOFF_O, oB, nullptr, out, out,
                                   nullptr, NP, HID_, HID_, 0, 0);

    // ---- conv2 ----
    k_lnh<<<LNB, 256>>>(out, lnPoG, lnPoB, hnh);
    k_conv_gather<<<NTOT, 64>>>(es);
    gemm_mma<<<g256, 256, GSMEM>>>(ah, whi+WOFF_POST, wlo+WOFF_POST, postB, cd, out, out,
                                   nullptr, NP, HID_, HID_, 1, 0);

    // ---- FFN ----
    k_lnh<<<LNB, 256>>>(out, lnFfG, lnFfB, ah);
    gemm_mma<<<g512, 256, GSMEM>>>(ah, whi+WOFF_F1, wlo+WOFF_F1, fB1, nullptr, nullptr,
                                   nullptr, fh, NP, HID_, 512, 0, 1);
    gemm_mma<<<g256, 256, GSMEM>>>(fh, whi+WOFF_F2, wlo+WOFF_F2, fB2, nullptr, out, out,
                                   nullptr, NP, 512, HID_, 0, 0);
}

// round 16
// speedup vs baseline: 1.3739x; 1.2281x over previous
#include <cuda_runtime.h>
#include <cuda_fp16.h>
#include <math.h>

#define T_   2
#define NP   25000
#define EP   200000
#define HID_ 256
#define NTOT (T_*NP)
#define E2   (2*EP)

// ---------------- scratch (static __device__ — no allocations) ----------------
__device__ __half g_hnh[(size_t)T_*NP*HID_];      // fp16 LN out (conv paths)
__device__ float  g_qkv[(size_t)NTOT*768];        // fp32 q|k|v per node
__device__ float  g_sc [(size_t)E2*8];            // ex overflow (deg>ECACHE only)
__device__ float  g_cs [T_*NP];
__device__ float  g_cd [T_*NP];
__device__ float  g_qkvb[T_*768];
__device__ int    g_degs[T_*NP];
__device__ int    g_degd[T_*NP];
__device__ int    g_bsum[256];
// CSR by global dst node
__device__ int    g_off [NTOT + 1];
__device__ int    g_fill[NTOT];
__device__ int    g_csr [E2];
// fp16 A operands
__device__ __half g_ah[(size_t)NTOT*HID_];
__device__ __half g_fh[(size_t)NTOT*512];
// fp16 weights, layout [matrix][t][N][K]
#define WCVT_TOTAL 1310720
__device__ __half g_wh[WCVT_TOTAL];
#define WOFF_PRE  0
#define WOFF_POST 131072
#define WOFF_QKV  262144
#define WOFF_O    655360
#define WOFF_F1   786432
#define WOFF_F2   1048576

// ---------------- mma / async helpers ----------------
__device__ __forceinline__ unsigned smem_u32(const void* p) {
    unsigned a;
    asm("{ .reg .u64 t; cvta.to.shared.u64 t, %1; cvt.u32.u64 %0, t; }" : "=r"(a) : "l"(p));
    return a;
}
#define LDM4(r, a) \
    asm volatile("ldmatrix.sync.aligned.m8n8.x4.shared.b16 {%0,%1,%2,%3}, [%4];" \
        : "=r"((r)[0]),"=r"((r)[1]),"=r"((r)[2]),"=r"((r)[3]) : "r"(a))
#define MMA_F16(c, a, b0, b1) \
    asm volatile("mma.sync.aligned.m16n8k16.row.col.f32.f16.f16.f32 " \
        "{%0,%1,%2,%3}, {%4,%5,%6,%7}, {%8,%9}, {%0,%1,%2,%3};" \
        : "+f"((c)[0]),"+f"((c)[1]),"+f"((c)[2]),"+f"((c)[3]) \
        : "r"((a)[0]),"r"((a)[1]),"r"((a)[2]),"r"((a)[3]), "r"(b0),"r"(b1))
#define CP16(dst, src) \
    asm volatile("cp.async.cg.shared.global [%0], [%1], 16;" :: "r"(dst), "l"(src) : "memory")
#define CP_COMMIT() asm volatile("cp.async.commit_group;" ::: "memory")
#define CP_WAIT0()  asm volatile("cp.async.wait_group 0;" ::: "memory")

__device__ __forceinline__ void store_h4(__half* dst, float4 v) {
    __half2 p0 = __floats2half2_rn(v.x, v.y);
    __half2 p1 = __floats2half2_rn(v.z, v.w);
    uint2 u;
    u.x = *(unsigned*)&p0; u.y = *(unsigned*)&p1;
    *(uint2*)dst = u;
}
__device__ __forceinline__ float4 load_h4(const __half* src) {
    uint2 u = *(const uint2*)src;
    __half2 p0 = *(__half2*)&u.x;
    __half2 p1 = *(__half2*)&u.y;
    float2 f0 = __half22float2(p0);
    float2 f1 = __half22float2(p1);
    return make_float4(f0.x, f0.y, f1.x, f1.y);
}
__device__ __forceinline__ float warp_sum(float v) {
    #pragma unroll
    for (int o = 16; o; o >>= 1) v += __shfl_xor_sync(0xffffffffu, v, o);
    return v;
}

// ---------------- degree + CSR build ----------------
__global__ void k_deg(const int* __restrict__ es, const int* __restrict__ ed) {
    int gid = blockIdx.x * blockDim.x + threadIdx.x;
    if (gid >= E2) return;
    int et = gid / EP;
    atomicAdd(&g_degs[et*NP + es[gid]], 1);
    atomicAdd(&g_degd[et*NP + ed[gid]], 1);
}

__global__ void k_degnorm() {
    int n = blockIdx.x * blockDim.x + threadIdx.x;
    if (n >= NP) return;
    #pragma unroll
    for (int et = 0; et < 2; et++) {
        g_cs[et*NP + n]       = rsqrtf((float)max(g_degs[et*NP + n], 1));
        g_cd[(1-et)*NP + n]   = rsqrtf((float)max(g_degd[et*NP + n], 1));
    }
}

// ---------------- parallel exclusive scan of in-degrees -> g_off ----------------
__global__ void k_scan1() {
    __shared__ int wsum[8];
    int tid = threadIdx.x, lane = tid & 31, wid = tid >> 5;
    int g = blockIdx.x * 256 + tid;
    int deg = 0;
    if (g < NTOT) {
        int dt = g / NP, n = g - dt * NP;
        deg = g_degd[(1 - dt) * NP + n];
    }
    int x = deg;
    #pragma unroll
    for (int o = 1; o < 32; o <<= 1) { int y = __shfl_up_sync(~0u, x, o); if (lane >= o) x += y; }
    if (lane == 31) wsum[wid] = x;
    __syncthreads();
    if (tid == 0) { int s = 0; for (int i = 0; i < 8; i++) { int t2 = wsum[i]; wsum[i] = s; s += t2; } }
    __syncthreads();
    if (g < NTOT) g_off[g] = wsum[wid] + x - deg;
    if (tid == 255) g_bsum[blockIdx.x] = wsum[7] + x;
}

__global__ void k_scan2() {
    __shared__ int wsum[8];
    int tid = threadIdx.x, lane = tid & 31, wid = tid >> 5;
    int v = (tid < 196) ? g_bsum[tid] : 0;
    int x = v;
    #pragma unroll
    for (int o = 1; o < 32; o <<= 1) { int y = __shfl_up_sync(~0u, x, o); if (lane >= o) x += y; }
    if (lane == 31) wsum[wid] = x;
    __syncthreads();
    if (tid == 0) { int s = 0; for (int i = 0; i < 8; i++) { int t2 = wsum[i]; wsum[i] = s; s += t2; } }
    __syncthreads();
    int excl = wsum[wid] + x - v;
    if (tid < 196) g_bsum[tid] = excl;
    if (tid == 195) g_off[NTOT] = excl + v;
}

__global__ void k_scan3() {
    int g = blockIdx.x * 256 + threadIdx.x;
    if (g < NTOT) g_off[g] += g_bsum[blockIdx.x];
}

__global__ void k_fill(const int* __restrict__ ed) {
    int gid = blockIdx.x * blockDim.x + threadIdx.x;
    if (gid >= E2) return;
    int et = gid / EP;
    int gnode = (1 - et) * NP + ed[gid];
    int pos = g_off[gnode] + atomicAdd(&g_fill[gnode], 1);
    g_csr[pos] = gid;
}

// ---------------- layernorm: warp per node, fp16 out to dst ----------------
__global__ void k_lnh(const float* __restrict__ x, const float* __restrict__ g,
                      const float* __restrict__ b, __half* __restrict__ dst) {
    int gn = blockIdx.x * 8 + (threadIdx.x >> 5);
    int lane = threadIdx.x & 31;
    int t = gn / NP;
    size_t base = (size_t)gn * HID_ + lane * 8;
    float4 v0 = *(const float4*)&x[base];
    float4 v1 = *(const float4*)&x[base + 4];
    float s = v0.x+v0.y+v0.z+v0.w + v1.x+v1.y+v1.z+v1.w;
    float mu = warp_sum(s) * (1.0f / HID_);
    float d0x=v0.x-mu, d0y=v0.y-mu, d0z=v0.z-mu, d0w=v0.w-mu;
    float d1x=v1.x-mu, d1y=v1.y-mu, d1z=v1.z-mu, d1w=v1.w-mu;
    float ss = d0x*d0x+d0y*d0y+d0z*d0z+d0w*d0w + d1x*d1x+d1y*d1y+d1z*d1z+d1w*d1w;
    float rstd = rsqrtf(warp_sum(ss) * (1.0f / HID_) + 1e-5f);
    size_t pb = (size_t)t * HID_ + lane * 8;
    float4 g0 = *(const float4*)&g[pb],  g1 = *(const float4*)&g[pb + 4];
    float4 b0 = *(const float4*)&b[pb],  b1 = *(const float4*)&b[pb + 4];
    float4 o0, o1;
    o0.x = d0x*rstd*g0.x + b0.x; o0.y = d0y*rstd*g0.y + b0.y;
    o0.z = d0z*rstd*g0.z + b0.z; o0.w = d0w*rstd*g0.w + b0.w;
    o1.x = d1x*rstd*g1.x + b1.x; o1.y = d1y*rstd*g1.y + b1.y;
    o1.z = d1z*rstd*g1.z + b1.z; o1.w = d1w*rstd*g1.w + b1.w;
    store_h4(&dst[base],     o0);
    store_h4(&dst[base + 4], o1);
}

// ---------------- conv aggregation: CSR gather (fp16 rows), fp16 out ----------------
__global__ void __launch_bounds__(64) k_conv_gather(const int* __restrict__ es) {
    int gnode = blockIdx.x;
    int tid = threadIdx.x;
    int off = g_off[gnode], end = g_off[gnode + 1];
    int dt = gnode / NP;
    int et = 1 - dt;
    float4 acc = make_float4(0.f, 0.f, 0.f, 0.f);
    for (int i = off; i < end; i++) {
        int eid = g_csr[i];
        int src = es[eid];
        float w = g_cs[et*NP + src];
        float4 hv = load_h4(&g_hnh[((size_t)et*NP + src)*HID_ + tid*4]);
        acc.x += hv.x*w; acc.y += hv.y*w; acc.z += hv.z*w; acc.w += hv.w*w;
    }
    store_h4(&g_ah[(size_t)gnode*HID_ + tid*4], acc);
}

// ---------------- fused attention: score+exp+den+gather, fp16 out ----------------
// qkv layout: [node][ q(0:256) | k(256:512) | v(512:768) ] fp32.
// ex values cached in SMEM for the first ECACHE edges; overflow spills to g_sc.
#define ECACHE 64
__global__ void __launch_bounds__(64) k_attn(const float* __restrict__ qkv,
                                             const int* __restrict__ es) {
    __shared__ float sq[HID_];
    __shared__ float sden[2][8];
    __shared__ float sex[ECACHE * 8];
    __shared__ int ssrc[ECACHE];
    int gnode = blockIdx.x, tid = threadIdx.x, lane = tid & 31, wid = tid >> 5;
    int off = g_off[gnode], deg = g_off[gnode + 1] - off;

    *(float4*)&sq[tid*4] = *(const float4*)&qkv[(size_t)gnode*768 + tid*4];
    int ncache = (deg < ECACHE) ? deg : ECACHE;
    for (int i = tid; i < ncache; i += 64) {
        int eid = g_csr[off + i];
        int et = eid / EP;
        ssrc[i] = es[eid] + (et ? NP : 0);
    }
    __syncthreads();

    float denAcc = 0.f;
    for (int i = wid; i < deg; i += 2) {
        int sg;
        if (i < ECACHE) sg = ssrc[i];
        else { int eid = g_csr[off + i]; int et = eid / EP; sg = es[eid] + (et ? NP : 0); }
        const float* kv = &qkv[(size_t)sg * 768 + 256];
        float myex = 0.f;
        #pragma unroll
        for (int hh = 0; hh < 8; hh++) {
            float p = sq[hh*32 + lane] * kv[hh*32 + lane];
            p = warp_sum(p);
            float s = fminf(fmaxf(p * 0.17677669529663687f, -5.0f), 5.0f);
            float ex = expf(s);   // s in [-5,5]: no overflow; max-shift cancels exactly
            if (lane == hh) myex = ex;
        }
        if (lane < 8) {
            if (i < ECACHE) sex[i*8 + lane] = myex;
            else            g_sc[(size_t)(off + i)*8 + lane] = myex;
            denAcc += myex;
        }
    }
    if (lane < 8) sden[wid][lane] = denAcc;
    __syncthreads();

    int hh = tid >> 3;
    float den = sden[0][hh] + sden[1][hh];
    float rden = (den > 0.f) ? 1.0f / den : 0.f;
    float4 acc = make_float4(0.f, 0.f, 0.f, 0.f);
    for (int i = 0; i < deg; i++) {
        int sg; float ex;
        if (i < ECACHE) { sg = ssrc[i]; ex = sex[i*8 + hh]; }
        else {
            int eid = g_csr[off + i]; int et = eid / EP;
            sg = es[eid] + (et ? NP : 0);
            ex = g_sc[(size_t)(off + i)*8 + hh];
        }
        float alpha = ex * rden;
        const float4 vv = *(const float4*)&qkv[(size_t)sg*768 + 512 + tid*4];
        acc.x += vv.x*alpha; acc.y += vv.y*alpha; acc.z += vv.z*alpha; acc.w += vv.w*alpha;
    }
    store_h4(&g_ah[(size_t)gnode*HID_ + tid*4], acc);
}

// ---------------- all-weights convert to fp16 (one launch) ----------------
__global__ void k_wconv_all(const float* __restrict__ preW, const float* __restrict__ postW,
                            const float* __restrict__ qW, const float* __restrict__ kW,
                            const float* __restrict__ vW, const float* __restrict__ oW,
                            const float* __restrict__ f1W, const float* __restrict__ f2W) {
    int gid = blockIdx.x * 256 + threadIdx.x;
    if (gid >= WCVT_TOTAL) return;
    float x;
    if (gid < 262144) {                       // PRE, POST: [t][256][256]
        const float* W = (gid < 131072) ? preW : postW;
        int loc = gid & 131071;
        int t = loc >> 16, o = loc & 65535;
        int n = o >> 8, kk = o & 255;
        x = W[t*65536 + kk*256 + n];
    } else if (gid < 655360) {                // QKV: [t][768][256]
        int loc = gid - 262144;
        int t = loc / 196608, r = loc % 196608;
        int n7 = r >> 8, kk = r & 255;
        const float* W; int n;
        if (n7 < 256)      { W = qW; n = n7; }
        else if (n7 < 512) { W = kW; n = n7 - 256; }
        else               { W = vW; n = n7 - 512; }
        x = W[t*65536 + kk*256 + n];
    } else if (gid < 786432) {                // O: [t][256][256]
        int loc = gid - 655360;
        int t = loc >> 16, o = loc & 65535;
        int n = o >> 8, kk = o & 255;
        x = oW[t*65536 + kk*256 + n];
    } else if (gid < 1048576) {               // F1: [t][512][256]
        int loc = gid - 786432;
        int t = loc >> 17, o = loc & 131071;
        int n = o >> 8, kk = o & 255;
        x = f1W[t*131072 + kk*512 + n];
    } else {                                  // F2: [t][256][512]
        int loc = gid - 1048576;
        int t = loc >> 17, o = loc & 131071;
        int n = o >> 9, kk = o & 511;
        x = f2W[t*131072 + kk*256 + n];
    }
    g_wh[gid] = __float2half_rn(x);
}

__global__ void k_qkvb(const float* __restrict__ qB, const float* __restrict__ kB,
                       const float* __restrict__ vB) {
    int i = blockIdx.x * 256 + threadIdx.x;
    if (i >= T_ * 768) return;
    int t = i / 768, c = i % 768;
    g_qkvb[i] = (c < 256) ? qB[t*256 + c] : (c < 512) ? kB[t*256 + c - 256] : vB[t*256 + c - 512];
}

// ---------------- fp16 tensor GEMM: D = A*B, 2-stage cp.async, K-chunk 64 ----------------
// A fp16 [t][M][K]; B fp16 [t][N][K]. CTA 128x128, 8 warps (4m x 2n).
// Single barrier per chunk iteration.
#define PAD 72
#define ST_A   (128*PAD)
#define ST_ALL (2*128*PAD)
#define GSMEM  (2*ST_ALL*2)

__global__ void __launch_bounds__(256, 2) gemm_mma(
    const __half* __restrict__ A_g, const __half* __restrict__ B_g,
    const float* __restrict__ bias, const float* __restrict__ rowscale,
    const float* __restrict__ resid, float* __restrict__ C,
    __half* __restrict__ Ch,
    int M, int K, int N, int wswap, int dogelu)
{
    extern __shared__ __half smem[];

    int tid = threadIdx.x;
    int warp = tid >> 5, lane = tid & 31;
    int wm = warp & 3, wn = warp >> 2;
    int t = blockIdx.z;
    int wi = wswap ? (1 - t) : t;

    A_g  += (size_t)t  * M * K;
    B_g  += (size_t)wi * K * N;
    bias += (size_t)wi * N;
    const float* rs = rowscale ? rowscale + (size_t)t * M : nullptr;
    const float* rd = resid ? resid + (size_t)t * M * N : nullptr;
    C  += (size_t)t * M * N;
    if (Ch) Ch += (size_t)t * M * N;

    int m0 = blockIdx.y * 128, n0 = blockIdx.x * 128;

    float acc[2][8][4];
    #pragma unroll
    for (int i = 0; i < 2; i++)
        #pragma unroll
        for (int j = 0; j < 8; j++)
            #pragma unroll
            for (int l = 0; l < 4; l++) acc[i][j][l] = 0.f;

    int lrow = lane & 7, lsel = lane >> 3;
    int a_r = (lsel & 1) * 8 + lrow;
    int a_c = (lsel >> 1) * 8;
    int b_r = (lsel >> 1) * 8 + lrow;
    int b_c = (lsel & 1) * 8;

    unsigned usm = smem_u32(smem);
    int grow = tid >> 3, gseg = tid & 7;    // chunk row = 64 elts = 8x16B segs
    int nchunks = K >> 6;

    {
        unsigned base = usm;
        #pragma unroll
        for (int i = 0; i < 4; i++) {
            int row = grow + i * 32;
            unsigned loc = 2u * (unsigned)(row * PAD + gseg * 8);
            size_t goa = (size_t)(m0 + row) * K + (gseg << 3);
            size_t gob = (size_t)(n0 + row) * K + (gseg << 3);
            CP16(base + loc,           &A_g[goa]);
            CP16(base + 2u*ST_A + loc, &B_g[gob]);
        }
        CP_COMMIT();
    }

    for (int c = 0; c < nchunks; c++) {
        int s = c & 1;
        unsigned base = usm + 2u * (unsigned)(s * ST_ALL);
        unsigned ua = base, ub = base + 2u*ST_A;

        CP_WAIT0();
        __syncthreads();

        if (c + 1 < nchunks) {
            int koff = (c + 1) << 6;
            unsigned nb = usm + 2u * (unsigned)((1 - s) * ST_ALL);
            #pragma unroll
            for (int i = 0; i < 4; i++) {
                int row = grow + i * 32;
                unsigned loc = 2u * (unsigned)(row * PAD + gseg * 8);
                size_t goa = (size_t)(m0 + row) * K + koff + (gseg << 3);
                size_t gob = (size_t)(n0 + row) * K + koff + (gseg << 3);
                CP16(nb + loc,           &A_g[goa]);
                CP16(nb + 2u*ST_A + loc, &B_g[gob]);
            }
            CP_COMMIT();
        }

        #pragma unroll
        for (int ks = 0; ks < 4; ks++) {
            int kk = ks * 16;
            unsigned ah[2][4];
            #pragma unroll
            for (int mt = 0; mt < 2; mt++) {
                unsigned off = 2u * (unsigned)((wm*32 + mt*16 + a_r) * PAD + kk + a_c);
                LDM4(ah[mt], ua + off);
            }
            #pragma unroll
            for (int bi = 0; bi < 4; bi++) {
                unsigned off = 2u * (unsigned)((wn*64 + bi*16 + b_r) * PAD + kk + b_c);
                unsigned bh[4];
                LDM4(bh, ub + off);
                #pragma unroll
                for (int mt = 0; mt < 2; mt++) {
                    #pragma unroll
                    for (int j = 0; j < 2; j++) {
                        MMA_F16(acc[mt][bi*2 + j], ah[mt], bh[j*2], bh[j*2+1]);
                    }
                }
            }
        }
        // no trailing __syncthreads: next iteration's post-wait barrier
        // orders stage reuse.
    }

    int g = lane >> 2, tig = lane & 3;
    #pragma unroll
    for (int mt = 0; mt < 2; mt++) {
        #pragma unroll
        for (int nt = 0; nt < 8; nt++) {
            int col = n0 + wn*64 + nt*8 + tig*2;
            float b0 = bias[col], b1 = bias[col+1];
            #pragma unroll
            for (int half = 0; half < 2; half++) {
                int r = m0 + wm*32 + mt*16 + g + half*8;
                if (r >= M) continue;
                float scale = rs ? rs[r] : 1.0f;
                size_t idx = (size_t)r * N + col;
                float2 o;
                o.x = acc[mt][nt][half*2+0] * scale + b0;
                o.y = acc[mt][nt][half*2+1] * scale + b1;
                if (rd) {
                    const float2 rv = *(const float2*)&rd[idx];
                    o.x += rv.x; o.y += rv.y;
                }
                if (dogelu) {
                    o.x = 0.5f*o.x*(1.0f+erff(o.x*0.70710678118654752f));
                    o.y = 0.5f*o.y*(1.0f+erff(o.y*0.70710678118654752f));
                }
                if (Ch) {
                    __half2 p = __floats2half2_rn(o.x, o.y);
                    *(unsigned*)&Ch[idx] = *(unsigned*)&p;
                } else {
                    *(float2*)&C[idx] = o;
                }
            }
        }
    }
}

// ---------------- host orchestration ----------------
extern "C" void kernel_launch(void* const* d_in, const int* in_sizes, int n_in,
                              void* d_out, int out_size) {
    const float* h      = (const float*)d_in[0];
    const int*   es     = (const int*)  d_in[1];
    const int*   ed     = (const int*)  d_in[2];
    const float* preW   = (const float*)d_in[3];
    const float* preB   = (const float*)d_in[4];
    const float* postW  = (const float*)d_in[5];
    const float* postB  = (const float*)d_in[6];
    const float* qW     = (const float*)d_in[7];
    const float* qB     = (const float*)d_in[8];
    const float* kW     = (const float*)d_in[9];
    const float* kB     = (const float*)d_in[10];
    const float* vW     = (const float*)d_in[11];
    const float* vB     = (const float*)d_in[12];
    const float* oW     = (const float*)d_in[13];
    const float* oB     = (const float*)d_in[14];
    const float* fW1    = (const float*)d_in[15];
    const float* fB1    = (const float*)d_in[16];
    const float* fW2    = (const float*)d_in[17];
    const float* fB2    = (const float*)d_in[18];
    const float* lnPreG = (const float*)d_in[19];
    const float* lnPreB = (const float*)d_in[20];
    const float* lnAtG  = (const float*)d_in[21];
    const float* lnAtB  = (const float*)d_in[22];
    const float* lnPoG  = (const float*)d_in[23];
    const float* lnPoB  = (const float*)d_in[24];
    const float* lnFfG  = (const float*)d_in[25];
    const float* lnFfB  = (const float*)d_in[26];
    float* out = (float*)d_out;

    float *qkv, *cd, *qkvb;
    __half *wh, *ah, *fh, *hnh;
    int *degs, *degd, *fill;
    cudaGetSymbolAddress((void**)&hnh,  g_hnh);
    cudaGetSymbolAddress((void**)&qkv,  g_qkv);
    cudaGetSymbolAddress((void**)&cd,   g_cd);
    cudaGetSymbolAddress((void**)&qkvb, g_qkvb);
    cudaGetSymbolAddress((void**)&degs, g_degs);
    cudaGetSymbolAddress((void**)&degd, g_degd);
    cudaGetSymbolAddress((void**)&fill, g_fill);
    cudaGetSymbolAddress((void**)&wh,   g_wh);
    cudaGetSymbolAddress((void**)&ah,   g_ah);
    cudaGetSymbolAddress((void**)&fh,   g_fh);

    cudaFuncSetAttribute(gemm_mma, cudaFuncAttributeMaxDynamicSharedMemorySize, GSMEM);

    static cudaStream_t s1 = nullptr;
    static cudaEvent_t evF = nullptr, evJ = nullptr;
    if (!s1) {
        cudaStreamCreateWithFlags(&s1, cudaStreamNonBlocking);
        cudaEventCreateWithFlags(&evF, cudaEventDisableTiming);
        cudaEventCreateWithFlags(&evJ, cudaEventDisableTiming);
    }

    const dim3 g256(2, 196, 2);
    const dim3 g768(6, 196, 2);
    const dim3 g512(4, 196, 2);
    const int NB = (NTOT + 255) / 256;   // 196
    const int LNB = NTOT / 8;            // 6250

    // ---- fork: CSR/degree chain on s1, weight convert + LN1 on main ----
    cudaEventRecord(evF, 0);
    cudaStreamWaitEvent(s1, evF, 0);

    cudaMemsetAsync(degs, 0, sizeof(int) * T_ * NP, s1);
    cudaMemsetAsync(degd, 0, sizeof(int) * T_ * NP, s1);
    cudaMemsetAsync(fill, 0, sizeof(int) * NTOT, s1);
    k_deg<<<(E2 + 255)/256, 256, 0, s1>>>(es, ed);
    k_degnorm<<<(NP + 255)/256, 256, 0, s1>>>();
    k_scan1<<<NB, 256, 0, s1>>>();
    k_scan2<<<1, 256, 0, s1>>>();
    k_scan3<<<NB, 256, 0, s1>>>();
    k_fill<<<(E2 + 255)/256, 256, 0, s1>>>(ed);
    cudaEventRecord(evJ, s1);

    k_wconv_all<<<WCVT_TOTAL/256, 256>>>(preW, postW, qW, kW, vW, oW, fW1, fW2);
    k_qkvb<<<(T_*768 + 255)/256, 256>>>(qB, kB, vB);
    k_lnh<<<LNB, 256>>>(h, lnPreG, lnPreB, hnh);

    cudaStreamWaitEvent(0, evJ, 0);   // join before CSR consumers

    // ---- conv1 ----
    k_conv_gather<<<NTOT, 64>>>(es);
    gemm_mma<<<g256, 256, GSMEM>>>(ah, wh+WOFF_PRE, preB, cd, h, out,
                                   nullptr, NP, HID_, HID_, 1, 0);

    // ---- attention ----
    k_lnh<<<LNB, 256>>>(out, lnAtG, lnAtB, ah);
    gemm_mma<<<g768, 256, GSMEM>>>(ah, wh+WOFF_QKV, qkvb, nullptr, nullptr,
                                   qkv, nullptr, NP, HID_, 768, 0, 0);
    k_attn<<<NTOT, 64>>>(qkv, es);
    gemm_mma<<<g256, 256, GSMEM>>>(ah, wh+WOFF_O, oB, nullptr, out, out,
                                   nullptr, NP, HID_, HID_, 0, 0);

    // ---- conv2 ----
    k_lnh<<<LNB, 256>>>(out, lnPoG, lnPoB, hnh);
    k_conv_gather<<<NTOT, 64>>>(es);
    gemm_mma<<<g256, 256, GSMEM>>>(ah, wh+WOFF_POST, postB, cd, out, out,
                                   nullptr, NP, HID_, HID_, 1, 0);

    // ---- FFN ----
    k_lnh<<<LNB, 256>>>(out, lnFfG, lnFfB, ah);
    gemm_mma<<<g512, 256, GSMEM>>>(ah, wh+WOFF_F1, fB1, nullptr, nullptr,
                                   nullptr, fh, NP, HID_, 512, 0, 1);
    gemm_mma<<<g256, 256, GSMEM>>>(fh, wh+WOFF_F2, fB2, nullptr, out, out,
                                   nullptr, NP, 512, HID_, 0, 0);
}